// round 2
// baseline (speedup 1.0000x reference)
#include <cuda_runtime.h>
#include <math.h>

#define N_PTS   29696
#define N_INF   1024
#define NZ      32
#define KCLU    100
#define EPSF    1e-5f
#define INDEXF  29696.0f
#define NBLK_PTS 116          // N_PTS / 256
#define NBLK_RE  1856         // (1024/128) * (29696/128)

// ---------------- scratch (static device globals; no allocation) -------------
__device__ float g_buf2048[(size_t)N_PTS * 2048];   // h3, then d1
__device__ float g_bufA[(size_t)N_PTS * 512];       // h1, then d2
__device__ float g_bufB[(size_t)N_PTS * 512];       // h2, then d3
__device__ float g_z[(size_t)N_PTS * NZ];
__device__ float g_q[(size_t)N_PTS * KCLU];
__device__ float g_upart[NBLK_PTS * KCLU];
__device__ float g_Spart[NBLK_PTS];
__device__ float g_klpart[NBLK_PTS];
__device__ float g_repart[NBLK_RE];
__device__ int   g_cnt[KCLU];
__device__ float g_f[KCLU];

// ---------------- helpers ----------------------------------------------------
__device__ __forceinline__ float block_reduce_sum(float v, float* red) {
    int tid = threadIdx.x;
    red[tid] = v;
    __syncthreads();
    for (int s = blockDim.x / 2; s > 0; s >>= 1) {
        if (tid < s) red[tid] += red[tid + s];
        __syncthreads();
    }
    return red[0];
}

__global__ void init_kernel() {
    int tid = threadIdx.x;
    if (tid < KCLU) g_cnt[tid] = 0;
}

__global__ void fill_zero_kernel(float* p, int n) {
    int i = blockIdx.x * blockDim.x + threadIdx.x;
    if (i < n) p[i] = 0.0f;
}

// ---------------- fp32 tiled GEMM: C = act(A @ B + bias) ---------------------
// A: [M,K] row-major, B: [K,N] row-major. Requires M%BM==0, N%BN==0, K%BK==0.
template <int BM, int BN, int BK, int TM, int TN, bool RELU>
__global__ void sgemm_bias(const float* __restrict__ A, const float* __restrict__ B,
                           const float* __restrict__ bias, float* __restrict__ C,
                           int M, int N, int K) {
    constexpr int THREADS = (BM / TM) * (BN / TN);
    __shared__ float As[BK][BM];
    __shared__ float Bs[BK][BN];
    const int tid = threadIdx.x;
    const int bm = blockIdx.y * BM, bn = blockIdx.x * BN;
    const int tx = tid % (BN / TN);
    const int ty = tid / (BN / TN);

    float acc[TM][TN];
#pragma unroll
    for (int i = 0; i < TM; i++)
#pragma unroll
        for (int j = 0; j < TN; j++) acc[i][j] = 0.0f;

    constexpr int A_LD = (BM * BK) / (THREADS * 4);
    constexpr int B_LD = (BK * BN) / (THREADS * 4);

    for (int k0 = 0; k0 < K; k0 += BK) {
#pragma unroll
        for (int i = 0; i < A_LD; i++) {
            int idx = (tid + i * THREADS) * 4;
            int r = idx / BK, c = idx % BK;
            float4 v = *reinterpret_cast<const float4*>(&A[(size_t)(bm + r) * K + k0 + c]);
            As[c + 0][r] = v.x; As[c + 1][r] = v.y; As[c + 2][r] = v.z; As[c + 3][r] = v.w;
        }
#pragma unroll
        for (int i = 0; i < B_LD; i++) {
            int idx = (tid + i * THREADS) * 4;
            int r = idx / BN, c = idx % BN;
            *reinterpret_cast<float4*>(&Bs[r][c]) =
                *reinterpret_cast<const float4*>(&B[(size_t)(k0 + r) * N + bn + c]);
        }
        __syncthreads();
#pragma unroll
        for (int k = 0; k < BK; k++) {
            float ar[TM], br[TN];
#pragma unroll
            for (int i = 0; i < TM; i++) ar[i] = As[k][ty * TM + i];
#pragma unroll
            for (int j = 0; j < TN; j++) br[j] = Bs[k][tx * TN + j];
#pragma unroll
            for (int i = 0; i < TM; i++)
#pragma unroll
                for (int j = 0; j < TN; j++) acc[i][j] += ar[i] * br[j];
        }
        __syncthreads();
    }

#pragma unroll
    for (int i = 0; i < TM; i++) {
        int row = bm + ty * TM + i;
#pragma unroll
        for (int j = 0; j < TN; j++) {
            int col = bn + tx * TN + j;
            float v = acc[i][j] + bias[col];
            if (RELU) v = fmaxf(v, 0.0f);
            C[(size_t)row * N + col] = v;
        }
    }
}

// last GEMM fused with sum((A@B+bias - X)^2) partial reduction (no relu)
template <int BM, int BN, int BK, int TM, int TN>
__global__ void sgemm_sqdiff(const float* __restrict__ A, const float* __restrict__ B,
                             const float* __restrict__ bias, const float* __restrict__ X,
                             int M, int N, int K) {
    constexpr int THREADS = (BM / TM) * (BN / TN);
    __shared__ float As[BK][BM];
    __shared__ float Bs[BK][BN];
    __shared__ float red[THREADS];
    const int tid = threadIdx.x;
    const int bm = blockIdx.y * BM, bn = blockIdx.x * BN;
    const int tx = tid % (BN / TN);
    const int ty = tid / (BN / TN);

    float acc[TM][TN];
#pragma unroll
    for (int i = 0; i < TM; i++)
#pragma unroll
        for (int j = 0; j < TN; j++) acc[i][j] = 0.0f;

    constexpr int A_LD = (BM * BK) / (THREADS * 4);
    constexpr int B_LD = (BK * BN) / (THREADS * 4);

    for (int k0 = 0; k0 < K; k0 += BK) {
#pragma unroll
        for (int i = 0; i < A_LD; i++) {
            int idx = (tid + i * THREADS) * 4;
            int r = idx / BK, c = idx % BK;
            float4 v = *reinterpret_cast<const float4*>(&A[(size_t)(bm + r) * K + k0 + c]);
            As[c + 0][r] = v.x; As[c + 1][r] = v.y; As[c + 2][r] = v.z; As[c + 3][r] = v.w;
        }
#pragma unroll
        for (int i = 0; i < B_LD; i++) {
            int idx = (tid + i * THREADS) * 4;
            int r = idx / BN, c = idx % BN;
            *reinterpret_cast<float4*>(&Bs[r][c]) =
                *reinterpret_cast<const float4*>(&B[(size_t)(k0 + r) * N + bn + c]);
        }
        __syncthreads();
#pragma unroll
        for (int k = 0; k < BK; k++) {
            float ar[TM], br[TN];
#pragma unroll
            for (int i = 0; i < TM; i++) ar[i] = As[k][ty * TM + i];
#pragma unroll
            for (int j = 0; j < TN; j++) br[j] = Bs[k][tx * TN + j];
#pragma unroll
            for (int i = 0; i < TM; i++)
#pragma unroll
                for (int j = 0; j < TN; j++) acc[i][j] += ar[i] * br[j];
        }
        __syncthreads();
    }

    float lsum = 0.0f;
#pragma unroll
    for (int i = 0; i < TM; i++) {
        int row = bm + ty * TM + i;
#pragma unroll
        for (int j = 0; j < TN; j++) {
            int col = bn + tx * TN + j;
            float v = acc[i][j] + bias[col];
            float d = v - X[(size_t)row * N + col];
            lsum += d * d;
        }
    }
    float bs = block_reduce_sum(lsum, red);
    if (tid == 0) g_repart[blockIdx.y * gridDim.x + blockIdx.x] = bs;
}

// ---------------- clustering pass A ------------------------------------------
// per point: zp-normalize, dists to 100 clusters, q row, predict, partials.
__global__ void cluster_pass(const float* __restrict__ t1,
                             const float* __restrict__ clu,
                             float* __restrict__ out_predict) {
    __shared__ float cs[KCLU * NZ];
    __shared__ float u_s[KCLU];
    __shared__ float red[256];
    int tid = threadIdx.x;
    for (int i = tid; i < KCLU * NZ; i += 256) cs[i] = clu[i];
    if (tid < KCLU) u_s[tid] = 0.0f;
    __syncthreads();

    int p = blockIdx.x * 256 + tid;
    float zr[NZ];
    const float* zp = g_z + (size_t)p * NZ;
#pragma unroll
    for (int i = 0; i < NZ; i++) zr[i] = zp[i];

    float cm = (t1[p * 3 + 0] * 0.01f) * (t1[p * 3 + 1] * 0.01f) * (t1[p * 3 + 2] * 0.01f)
               * 0.99f + 1.0f;
    float s = 0.0f;
#pragma unroll
    for (int i = 0; i < NZ; i++) { zr[i] *= cm; s += zr[i]; }
    float mean = s * (1.0f / NZ);
    float var = 0.0f;
#pragma unroll
    for (int i = 0; i < NZ; i++) { float d = zr[i] - mean; var += d * d; }
    float isd = 1.0f / sqrtf(var * (1.0f / (NZ - 1)));
#pragma unroll
    for (int i = 0; i < NZ; i++) zr[i] = (zr[i] - mean) * isd;

    // pass 1: sum of unnormalized q (= eps + dist, since V_DOF = 1) and argmax
    float sumq = 0.0f, best = -1.0f;
    int bi = 0;
    for (int j = 0; j < KCLU; j++) {
        const float* c = &cs[j * NZ];
        float d = 0.0f;
#pragma unroll
        for (int i = 0; i < NZ; i++) { float t = zr[i] - c[i]; d += t * t; }
        float qu = EPSF + d;
        sumq += qu;
        if (qu > best) { best = qu; bi = j; }
    }
    out_predict[p] = (float)bi;
    atomicAdd(&g_cnt[bi], 1);

    float inv = 1.0f / sumq;
    float Sl = 0.0f;
    float* qrow = g_q + (size_t)p * KCLU;
    for (int j = 0; j < KCLU; j++) {
        const float* c = &cs[j * NZ];
        float d = 0.0f;
#pragma unroll
        for (int i = 0; i < NZ; i++) { float t = zr[i] - c[i]; d += t * t; }
        float qn = (EPSF + d) * inv;
        qrow[j] = qn;
        atomicAdd(&u_s[j], qn);
        float lq = logf(qn);
        float tq = (1.0f - qn) * (1.0f - qn) * lq * INDEXF;
        Sl += sqrtf(-1.0f / tq);
    }

    float Sblk = block_reduce_sum(Sl, red);
    if (tid == 0) g_Spart[blockIdx.x] = Sblk;
    __syncthreads();
    if (tid < KCLU) g_upart[blockIdx.x * KCLU + tid] = u_s[tid];
}

// ---------------- stats pass B (tiny, 1 block) --------------------------------
__global__ void stats_kernel() {
    __shared__ float u[KCLU];
    __shared__ float sred[128];
    int tid = threadIdx.x;
    if (tid < KCLU) {
        float s = 0.0f;
        for (int b = 0; b < NBLK_PTS; b++) s += g_upart[b * KCLU + tid];
        u[tid] = s;
    }
    float sp = (tid < NBLK_PTS) ? g_Spart[tid] : 0.0f;
    sred[tid] = sp;
    __syncthreads();
    for (int s = 64; s > 0; s >>= 1) {
        if (tid < s) sred[tid] += sred[tid + s];
        __syncthreads();
    }
    if (tid == 0) {
        float S = sred[0];
        float um = 0.0f;
        for (int j = 0; j < KCLU; j++) um += u[j];
        um /= KCLU;
        float uv = 0.0f;
        for (int j = 0; j < KCLU; j++) { float d = u[j] - um; uv += d * d; }
        float usd = sqrtf(uv / (KCLU - 1));

        float v[KCLU];
        float vm = 0.0f;
        for (int j = 0; j < KCLU; j++) {
            int c = g_cnt[j]; if (c < 1) c = 1;
            v[j] = sqrtf((float)c) * S;
            vm += v[j];
        }
        vm /= KCLU;
        float vv = 0.0f;
        for (int j = 0; j < KCLU; j++) { float d = v[j] - vm; vv += d * d; }
        float vsd = sqrtf(vv / (KCLU - 1));

        float umin = 1e30f, vmin = 1e30f;
        for (int j = 0; j < KCLU; j++) {
            float un = (u[j] - um) / usd;
            float vn = (v[j] - vm) / vsd;
            u[j] = un; v[j] = vn;
            if (un < umin) umin = un;
            if (vn < vmin) vmin = vn;
        }
        for (int j = 0; j < KCLU; j++) {
            g_f[j] = (u[j] - umin + 0.001f) + (v[j] - vmin + 0.001f) + 1.0f;
        }
    }
}

// ---------------- KL pass C ----------------------------------------------------
__global__ void kl_pass() {
    __shared__ float fs[KCLU];
    __shared__ float red[256];
    int tid = threadIdx.x;
    if (tid < KCLU) fs[tid] = g_f[tid];
    __syncthreads();
    int p = blockIdx.x * 256 + tid;
    const float* qrow = g_q + (size_t)p * KCLU;
    float sw = 0.0f;
    for (int j = 0; j < KCLU; j++) { float q = qrow[j]; sw += q * q / fs[j]; }
    float inv = 1.0f / sw;
    float kl = 0.0f;
    for (int j = 0; j < KCLU; j++) {
        float q = qrow[j];
        float pj = q * q / fs[j] * inv;
        kl += pj * (logf(pj) - logf(q));
    }
    float b = block_reduce_sum(kl, red);
    if (tid == 0) g_klpart[blockIdx.x] = b;
}

// ---------------- final loss (1 block) -----------------------------------------
__global__ void final_kernel(const float* __restrict__ clu, float* __restrict__ out) {
    __shared__ float red[256];
    int tid = threadIdx.x;
    float kl = 0.0f;
    for (int i = tid; i < NBLK_PTS; i += 256) kl += g_klpart[i];
    float re = 0.0f;
    for (int i = tid; i < NBLK_RE; i += 256) re += g_repart[i];
    float D = 0.0f;
    for (int idx = tid; idx < KCLU * KCLU; idx += 256) {
        int i = idx / KCLU, j = idx % KCLU;
        float d = 0.0f;
        for (int kk = 0; kk < NZ; kk++) {
            float t = clu[i * NZ + kk] - clu[j * NZ + kk];
            d += t * t;
        }
        D += d;
    }
    float kls = block_reduce_sum(kl, red);
    __syncthreads();
    float res = block_reduce_sum(re, red);
    __syncthreads();
    float Ds = block_reduce_sum(D, red);
    if (tid == 0) {
        float kl_loss = 0.01f * kls / ((float)N_PTS * (float)KCLU);
        float re_loss = res / ((float)N_PTS * (float)N_INF);
        float mean_d = Ds / (float)(KCLU * KCLU - KCLU);
        float loss = kl_loss + re_loss + 0.01f / mean_d;
        out[N_PTS] = loss;
    }
}

// ---------------- host ---------------------------------------------------------
extern "C" void kernel_launch(void* const* d_in, const int* in_sizes, int n_in,
                              void* d_out, int out_size) {
    const float* x   = (const float*)d_in[0];
    const float* t1  = (const float*)d_in[1];
    const float* clu = (const float*)d_in[2];
    const float* We1 = (const float*)d_in[3];  const float* be1 = (const float*)d_in[4];
    const float* We2 = (const float*)d_in[5];  const float* be2 = (const float*)d_in[6];
    const float* We3 = (const float*)d_in[7];  const float* be3 = (const float*)d_in[8];
    const float* Wz  = (const float*)d_in[9];  const float* bz  = (const float*)d_in[10];
    const float* Wd1 = (const float*)d_in[11]; const float* bd1 = (const float*)d_in[12];
    const float* Wd2 = (const float*)d_in[13]; const float* bd2 = (const float*)d_in[14];
    const float* Wd3 = (const float*)d_in[15]; const float* bd3 = (const float*)d_in[16];
    const float* Wxb = (const float*)d_in[17]; const float* bxb = (const float*)d_in[18];
    float* out = (float*)d_out;

    float *bufA, *bufB, *buf2048, *zb;
    cudaGetSymbolAddress((void**)&bufA, g_bufA);
    cudaGetSymbolAddress((void**)&bufB, g_bufB);
    cudaGetSymbolAddress((void**)&buf2048, g_buf2048);
    cudaGetSymbolAddress((void**)&zb, g_z);

    init_kernel<<<1, 128>>>();

    const int MB = N_PTS / 128;  // 232
    // encoder
    sgemm_bias<128, 128, 8, 8, 8, true><<<dim3(512 / 128, MB), 256>>>(x, We1, be1, bufA, N_PTS, 512, 1024);
    sgemm_bias<128, 128, 8, 8, 8, true><<<dim3(512 / 128, MB), 256>>>(bufA, We2, be2, bufB, N_PTS, 512, 512);
    sgemm_bias<128, 128, 8, 8, 8, true><<<dim3(2048 / 128, MB), 256>>>(bufB, We3, be3, buf2048, N_PTS, 2048, 512);
    sgemm_bias<128, 32, 32, 8, 2, false><<<dim3(1, MB), 256>>>(buf2048, Wz, bz, zb, N_PTS, 32, 2048);
    // decoder
    sgemm_bias<128, 128, 8, 8, 8, true><<<dim3(2048 / 128, MB), 256>>>(zb, Wd1, bd1, buf2048, N_PTS, 2048, 32);
    sgemm_bias<128, 128, 8, 8, 8, true><<<dim3(512 / 128, MB), 256>>>(buf2048, Wd2, bd2, bufA, N_PTS, 512, 2048);
    sgemm_bias<128, 128, 8, 8, 8, true><<<dim3(512 / 128, MB), 256>>>(bufA, Wd3, bd3, bufB, N_PTS, 512, 512);
    // x_bar GEMM fused with re_loss partial sums
    sgemm_sqdiff<128, 128, 8, 8, 8><<<dim3(1024 / 128, MB), 256>>>(bufB, Wxb, bxb, x, N_PTS, 1024, 512);

    // clustering
    cluster_pass<<<NBLK_PTS, 256>>>(t1, clu, out);
    stats_kernel<<<1, 128>>>();
    kl_pass<<<NBLK_PTS, 256>>>();
    final_kernel<<<1, 256>>>(clu, out);

    // zero any extra output slots beyond [predict..., loss]
    int extra = out_size - (N_PTS + 1);
    if (extra > 0) {
        fill_zero_kernel<<<(extra + 255) / 256, 256>>>(out + N_PTS + 1, extra);
    }
}

// round 6
// speedup vs baseline: 1.6800x; 1.6800x over previous
#include <cuda_runtime.h>
#include <math.h>
#include <stdint.h>

#define N_PTS   29696
#define NZ      32
#define KCLU    100
#define EPSF    1e-5f
#define INDEXF  29696.0f
#define NBLK_PTS 116          // N_PTS / 256
#define NBLK_RE  1856         // (1024/128) * (29696/128)
#define GAP_TAU 3e-4f

// ---------------- scratch (static device globals; no allocation) -------------
__device__ float g_P [(size_t)N_PTS * 2048];   // h3, then d1
__device__ float g_h1[(size_t)N_PTS * 512];    // h1, then d2
__device__ float g_h2[(size_t)N_PTS * 512];    // h2, then d3
__device__ float g_z [(size_t)N_PTS * NZ];
__device__ float g_q [(size_t)N_PTS * KCLU];
__device__ float g_wt[2048 * 512];             // transposed weights (reused per layer)
__device__ float g_upart[NBLK_PTS * KCLU];
__device__ float g_Spart[NBLK_PTS];
__device__ float g_klpart[NBLK_PTS];
__device__ float g_repart[NBLK_RE];
__device__ int   g_cnt[KCLU];
__device__ float g_f[KCLU];
__device__ int   g_nflag;
__device__ int   g_flaglist[N_PTS];

// ---------------- helpers ------------------------------------------------------
__device__ __forceinline__ float tf32_rna(float x) {
    uint32_t u;
    asm("cvt.rna.tf32.f32 %0, %1;" : "=r"(u) : "f"(x));
    return __uint_as_float(u);
}
#define MMA_TF32(c, a, b) \
    asm volatile("mma.sync.aligned.m16n8k8.row.col.f32.tf32.tf32.f32 " \
        "{%0,%1,%2,%3}, {%4,%5,%6,%7}, {%8,%9}, {%0,%1,%2,%3};" \
        : "+f"((c)[0]), "+f"((c)[1]), "+f"((c)[2]), "+f"((c)[3]) \
        : "r"((a)[0]), "r"((a)[1]), "r"((a)[2]), "r"((a)[3]), \
          "r"((b)[0]), "r"((b)[1]))

__global__ void init_kernel() {
    int tid = threadIdx.x;
    if (tid < KCLU) g_cnt[tid] = 0;
    if (tid == 0) g_nflag = 0;
}
__global__ void fill_zero_kernel(float* p, int n) {
    int i = blockIdx.x * blockDim.x + threadIdx.x;
    if (i < n) p[i] = 0.0f;
}
// Wt[n,k] = W[k,n]; dims multiples of 32. grid(Nd/32, Kd/32), block(32,8)
__global__ void transpose_w(const float* __restrict__ in, float* __restrict__ out,
                            int Kd, int Nd) {
    __shared__ float t[32][33];
    int n0 = blockIdx.x * 32, k0 = blockIdx.y * 32;
    int tx = threadIdx.x, ty = threadIdx.y;
    for (int i = ty; i < 32; i += 8) t[i][tx] = in[(size_t)(k0 + i) * Nd + n0 + tx];
    __syncthreads();
    for (int i = ty; i < 32; i += 8) out[(size_t)(n0 + i) * Kd + k0 + tx] = t[tx][i];
}

// ---------------- tf32 mma.sync GEMM -------------------------------------------
// C[M,N] = epi(A[M,K] @ Wt[N,K]^T + bias).
// NT=2: 3xTF32 Dekker split. NT=1: single tf32 pass.
// EPI: 0 relu-store, 1 plain store, 2 fused sum((v-X)^2) block partials.
template <int BN, int NT, int EPI>
__global__ void __launch_bounds__(256, 1)
mma_gemm(const float* __restrict__ A, const float* __restrict__ Bt,
         const float* __restrict__ bias, float* __restrict__ C,
         const float* __restrict__ X, float* __restrict__ part,
         int N, int K) {
    extern __shared__ float smf[];
    constexpr int LDA = 36;
    constexpr int A_TILE_F = 128 * LDA;
    constexpr int B_TILE_F = BN * LDA;
    constexpr int STAGE_F = NT * (A_TILE_F + B_TILE_F);
    constexpr int NTL = BN / 32;
    constexpr int WN = BN / 4;
    constexpr int B_LD = (BN * 8) / 256;

    const int tid = threadIdx.x;
    const int wid = tid >> 5;
    const int lane = tid & 31;
    const int g = lane >> 2;
    const int t = lane & 3;
    const int warp_m = wid >> 2;
    const int warp_n = wid & 3;
    const int bm = blockIdx.y * 128, bn = blockIdx.x * BN;

    float acc[4][NTL][4];
#pragma unroll
    for (int mt = 0; mt < 4; mt++)
#pragma unroll
        for (int nt = 0; nt < NTL; nt++)
#pragma unroll
            for (int i = 0; i < 4; i++) acc[mt][nt][i] = 0.0f;

    const int NC = K >> 5;
    float4 pa[4], pb[B_LD];

    auto loadG = [&](int c) {
        const int k0 = c << 5;
#pragma unroll
        for (int i = 0; i < 4; i++) {
            int idx = tid + i * 256;
            int r = idx >> 3, c4 = idx & 7;
            pa[i] = *reinterpret_cast<const float4*>(&A[(size_t)(bm + r) * K + k0 + c4 * 4]);
        }
#pragma unroll
        for (int i = 0; i < B_LD; i++) {
            int idx = tid + i * 256;
            int r = idx >> 3, c4 = idx & 7;
            pb[i] = *reinterpret_cast<const float4*>(&Bt[(size_t)(bn + r) * K + k0 + c4 * 4]);
        }
    };
    auto storeS = [&](int s) {
        float* a0 = smf + s * STAGE_F;
        float* b0 = smf + s * STAGE_F + NT * A_TILE_F;
#pragma unroll
        for (int i = 0; i < 4; i++) {
            int idx = tid + i * 256;
            int r = idx >> 3, c4 = idx & 7;
            float4 v = pa[i], h;
            h.x = tf32_rna(v.x); h.y = tf32_rna(v.y); h.z = tf32_rna(v.z); h.w = tf32_rna(v.w);
            *reinterpret_cast<float4*>(&a0[r * LDA + c4 * 4]) = h;
            if (NT == 2) {
                float4 l;
                l.x = tf32_rna(v.x - h.x); l.y = tf32_rna(v.y - h.y);
                l.z = tf32_rna(v.z - h.z); l.w = tf32_rna(v.w - h.w);
                *reinterpret_cast<float4*>(&a0[A_TILE_F + r * LDA + c4 * 4]) = l;
            }
        }
#pragma unroll
        for (int i = 0; i < B_LD; i++) {
            int idx = tid + i * 256;
            int r = idx >> 3, c4 = idx & 7;
            float4 v = pb[i], h;
            h.x = tf32_rna(v.x); h.y = tf32_rna(v.y); h.z = tf32_rna(v.z); h.w = tf32_rna(v.w);
            *reinterpret_cast<float4*>(&b0[r * LDA + c4 * 4]) = h;
            if (NT == 2) {
                float4 l;
                l.x = tf32_rna(v.x - h.x); l.y = tf32_rna(v.y - h.y);
                l.z = tf32_rna(v.z - h.z); l.w = tf32_rna(v.w - h.w);
                *reinterpret_cast<float4*>(&b0[B_TILE_F + r * LDA + c4 * 4]) = l;
            }
        }
    };
    auto compute = [&](int s) {
        const float* As0 = smf + s * STAGE_F;
        const float* As1 = As0 + A_TILE_F;
        const float* Bs0 = smf + s * STAGE_F + NT * A_TILE_F;
        const float* Bs1 = Bs0 + B_TILE_F;
#pragma unroll
        for (int ks = 0; ks < 4; ks++) {
            const int kk = ks * 8 + t;
            uint32_t bh[NTL][2], bl[NTL][2];
#pragma unroll
            for (int nt = 0; nt < NTL; nt++) {
                int nb = warp_n * WN + nt * 8 + g;
                bh[nt][0] = __float_as_uint(Bs0[nb * LDA + kk]);
                bh[nt][1] = __float_as_uint(Bs0[nb * LDA + kk + 4]);
                if (NT == 2) {
                    bl[nt][0] = __float_as_uint(Bs1[nb * LDA + kk]);
                    bl[nt][1] = __float_as_uint(Bs1[nb * LDA + kk + 4]);
                }
            }
#pragma unroll
            for (int mt = 0; mt < 4; mt++) {
                int mb = warp_m * 64 + mt * 16 + g;
                uint32_t ah[4];
                ah[0] = __float_as_uint(As0[mb * LDA + kk]);
                ah[1] = __float_as_uint(As0[(mb + 8) * LDA + kk]);
                ah[2] = __float_as_uint(As0[mb * LDA + kk + 4]);
                ah[3] = __float_as_uint(As0[(mb + 8) * LDA + kk + 4]);
#pragma unroll
                for (int nt = 0; nt < NTL; nt++) MMA_TF32(acc[mt][nt], ah, bh[nt]);
                if (NT == 2) {
                    uint32_t al[4];
                    al[0] = __float_as_uint(As1[mb * LDA + kk]);
                    al[1] = __float_as_uint(As1[(mb + 8) * LDA + kk]);
                    al[2] = __float_as_uint(As1[mb * LDA + kk + 4]);
                    al[3] = __float_as_uint(As1[(mb + 8) * LDA + kk + 4]);
#pragma unroll
                    for (int nt = 0; nt < NTL; nt++) {
                        MMA_TF32(acc[mt][nt], ah, bl[nt]);
                        MMA_TF32(acc[mt][nt], al, bh[nt]);
                    }
                }
            }
        }
    };

    loadG(0);
    storeS(0);
    __syncthreads();
#pragma unroll 1
    for (int c = 0; c < NC; c++) {
        if (c + 1 < NC) loadG(c + 1);
        compute(c & 1);
        if (c + 1 < NC) storeS((c + 1) & 1);
        __syncthreads();
    }

    float lsum = 0.0f;
#pragma unroll
    for (int mt = 0; mt < 4; mt++) {
#pragma unroll
        for (int nt = 0; nt < NTL; nt++) {
            int row = bm + warp_m * 64 + mt * 16 + g;
            int col = bn + warp_n * WN + nt * 8 + 2 * t;
            float b0 = bias[col], b1 = bias[col + 1];
            float v0 = acc[mt][nt][0] + b0, v1 = acc[mt][nt][1] + b1;
            float v2 = acc[mt][nt][2] + b0, v3 = acc[mt][nt][3] + b1;
            if (EPI == 0) {
                v0 = fmaxf(v0, 0.0f); v1 = fmaxf(v1, 0.0f);
                v2 = fmaxf(v2, 0.0f); v3 = fmaxf(v3, 0.0f);
            }
            size_t i0 = (size_t)row * N + col;
            size_t i1 = (size_t)(row + 8) * N + col;
            if (EPI == 2) {
                float2 x0 = *reinterpret_cast<const float2*>(&X[i0]);
                float2 x1 = *reinterpret_cast<const float2*>(&X[i1]);
                float d0 = v0 - x0.x, d1 = v1 - x0.y, d2 = v2 - x1.x, d3 = v3 - x1.y;
                lsum += d0 * d0 + d1 * d1 + d2 * d2 + d3 * d3;
            } else {
                float2 o0 = make_float2(v0, v1), o1 = make_float2(v2, v3);
                *reinterpret_cast<float2*>(&C[i0]) = o0;
                *reinterpret_cast<float2*>(&C[i1]) = o1;
            }
        }
    }
    if (EPI == 2) {
        __syncthreads();
        smf[tid] = lsum;
        __syncthreads();
        for (int s2 = 128; s2 > 0; s2 >>= 1) {
            if (tid < s2) smf[tid] += smf[tid + s2];
            __syncthreads();
        }
        if (tid == 0) part[blockIdx.y * gridDim.x + blockIdx.x] = smf[0];
    }
}

// ---------------- clustering pass A -------------------------------------------
__global__ void cluster_pass(const float* __restrict__ t1,
                             const float* __restrict__ clu,
                             float* __restrict__ out_predict) {
    __shared__ float cs[KCLU * NZ];
    __shared__ float u_s[KCLU];
    __shared__ float red[256];
    int tid = threadIdx.x;
    for (int i = tid; i < KCLU * NZ; i += 256) cs[i] = clu[i];
    if (tid < KCLU) u_s[tid] = 0.0f;
    __syncthreads();

    int p = blockIdx.x * 256 + tid;
    float zr[NZ];
    const float* zp = g_z + (size_t)p * NZ;
#pragma unroll
    for (int i = 0; i < NZ; i++) zr[i] = zp[i];

    float cm = (t1[p * 3 + 0] * 0.01f) * (t1[p * 3 + 1] * 0.01f) * (t1[p * 3 + 2] * 0.01f)
               * 0.99f + 1.0f;
    float s = 0.0f;
#pragma unroll
    for (int i = 0; i < NZ; i++) { zr[i] *= cm; s += zr[i]; }
    float mean = s * (1.0f / NZ);
    float var = 0.0f;
#pragma unroll
    for (int i = 0; i < NZ; i++) { float d = zr[i] - mean; var += d * d; }
    float isd = 1.0f / sqrtf(var * (1.0f / (NZ - 1)));
#pragma unroll
    for (int i = 0; i < NZ; i++) zr[i] = (zr[i] - mean) * isd;

    float sumq = 0.0f, best = -1.0f, best2 = -1.0f;
    int bi = 0;
    for (int j = 0; j < KCLU; j++) {
        const float* c = &cs[j * NZ];
        float d = 0.0f;
#pragma unroll
        for (int i = 0; i < NZ; i++) { float tt = zr[i] - c[i]; d += tt * tt; }
        float qu = EPSF + d;
        sumq += qu;
        if (qu > best) { best2 = best; best = qu; bi = j; }
        else if (qu > best2) best2 = qu;
    }
    out_predict[p] = (float)bi;
    atomicAdd(&g_cnt[bi], 1);
    if (best - best2 < GAP_TAU * best) {       // near-tie: flag for fp32 rescue
        int ii = atomicAdd(&g_nflag, 1);
        g_flaglist[ii] = p;
    }

    float inv = 1.0f / sumq;
    float Sl = 0.0f;
    float* qrow = g_q + (size_t)p * KCLU;
    for (int j = 0; j < KCLU; j++) {
        const float* c = &cs[j * NZ];
        float d = 0.0f;
#pragma unroll
        for (int i = 0; i < NZ; i++) { float tt = zr[i] - c[i]; d += tt * tt; }
        float qn = (EPSF + d) * inv;
        qrow[j] = qn;
        atomicAdd(&u_s[j], qn);
        float lq = logf(qn);
        float tq = (1.0f - qn) * (1.0f - qn) * lq * INDEXF;
        Sl += sqrtf(-1.0f / tq);
    }

    red[tid] = Sl;
    __syncthreads();
    for (int s2 = 128; s2 > 0; s2 >>= 1) {
        if (tid < s2) red[tid] += red[tid + s2];
        __syncthreads();
    }
    if (tid == 0) g_Spart[blockIdx.x] = red[0];
    __syncthreads();
    if (tid < KCLU) g_upart[blockIdx.x * KCLU + tid] = u_s[tid];
}

// ---------------- fp32 rescue for near-tie points ------------------------------
// Recomputes the full encoder chain in fp32 for flagged points; fixes predict/cnt.
#define RB 8
__global__ void __launch_bounds__(256, 1)
rescue_kernel(const float* __restrict__ x, const float* __restrict__ t1,
              const float* __restrict__ clu,
              const float* __restrict__ We1, const float* __restrict__ be1,
              const float* __restrict__ We2, const float* __restrict__ be2,
              const float* __restrict__ We3, const float* __restrict__ be3,
              const float* __restrict__ Wz,  const float* __restrict__ bz,
              float* __restrict__ out_predict) {
    extern __shared__ float sm[];
    float* xb  = sm;                 // RB*1024
    float* hh  = xb + RB * 1024;     // RB*2048
    float* s1b = hh + RB * 2048;     // RB*512
    float* s2b = s1b + RB * 512;     // RB*512
    float* zz  = s2b + RB * 512;     // RB*32
    float* dst = zz + RB * 32;       // 128
    const int tid = threadIdx.x;
    const int nf = g_nflag;

    for (int base = blockIdx.x * RB; base < nf; base += gridDim.x * RB) {
        const int cb = min(RB, nf - base);
        __syncthreads();
        for (int i = 0; i < RB; i++) {
            int p = g_flaglist[base + (i < cb ? i : 0)];
            for (int k = tid; k < 1024; k += 256)
                xb[i * 1024 + k] = x[(size_t)p * 1024 + k];
        }
        __syncthreads();
        // L1: 1024 -> 512 relu
        for (int n = tid; n < 512; n += 256) {
            float acc[RB] = {};
            for (int k = 0; k < 1024; k++) {
                float w = We1[(size_t)k * 512 + n];
#pragma unroll
                for (int i = 0; i < RB; i++) acc[i] += xb[i * 1024 + k] * w;
            }
            float b = be1[n];
#pragma unroll
            for (int i = 0; i < RB; i++) s1b[i * 512 + n] = fmaxf(acc[i] + b, 0.0f);
        }
        __syncthreads();
        // L2: 512 -> 512 relu
        for (int n = tid; n < 512; n += 256) {
            float acc[RB] = {};
            for (int k = 0; k < 512; k++) {
                float w = We2[(size_t)k * 512 + n];
#pragma unroll
                for (int i = 0; i < RB; i++) acc[i] += s1b[i * 512 + k] * w;
            }
            float b = be2[n];
#pragma unroll
            for (int i = 0; i < RB; i++) s2b[i * 512 + n] = fmaxf(acc[i] + b, 0.0f);
        }
        __syncthreads();
        // L3: 512 -> 2048 relu
        for (int n = tid; n < 2048; n += 256) {
            float acc[RB] = {};
            for (int k = 0; k < 512; k++) {
                float w = We3[(size_t)k * 2048 + n];
#pragma unroll
                for (int i = 0; i < RB; i++) acc[i] += s2b[i * 512 + k] * w;
            }
            float b = be3[n];
#pragma unroll
            for (int i = 0; i < RB; i++) hh[i * 2048 + n] = fmaxf(acc[i] + b, 0.0f);
        }
        __syncthreads();
        // Lz: 2048 -> 32 (no relu)
        if (tid < 32) {
            int n = tid;
            float acc[RB] = {};
            for (int k = 0; k < 2048; k++) {
                float w = Wz[(size_t)k * 32 + n];
#pragma unroll
                for (int i = 0; i < RB; i++) acc[i] += hh[i * 2048 + k] * w;
            }
            float b = bz[n];
#pragma unroll
            for (int i = 0; i < RB; i++) zz[i * 32 + n] = acc[i] + b;
        }
        __syncthreads();
        // standardize (one thread per point)
        if (tid < cb) {
            int i = tid;
            int p = g_flaglist[base + i];
            float cm = (t1[p * 3 + 0] * 0.01f) * (t1[p * 3 + 1] * 0.01f) *
                       (t1[p * 3 + 2] * 0.01f) * 0.99f + 1.0f;
            float s = 0.0f;
            for (int k = 0; k < NZ; k++) { zz[i * 32 + k] *= cm; s += zz[i * 32 + k]; }
            float mean = s * (1.0f / NZ);
            float var = 0.0f;
            for (int k = 0; k < NZ; k++) {
                float d = zz[i * 32 + k] - mean; var += d * d;
            }
            float isd = 1.0f / sqrtf(var * (1.0f / (NZ - 1)));
            for (int k = 0; k < NZ; k++) zz[i * 32 + k] = (zz[i * 32 + k] - mean) * isd;
        }
        __syncthreads();
        // exact distances + argmax fix
        for (int i = 0; i < cb; i++) {
            if (tid < KCLU) {
                float d = 0.0f;
                for (int k = 0; k < NZ; k++) {
                    float tt = zz[i * 32 + k] - clu[tid * NZ + k];
                    d += tt * tt;
                }
                dst[tid] = d;
            }
            __syncthreads();
            if (tid == 0) {
                float best = -1.0f; int bi = 0;
                for (int j = 0; j < KCLU; j++)
                    if (dst[j] > best) { best = dst[j]; bi = j; }
                int p = g_flaglist[base + i];
                int old = (int)out_predict[p];
                if (old != bi) {
                    atomicAdd(&g_cnt[old], -1);
                    atomicAdd(&g_cnt[bi], 1);
                    out_predict[p] = (float)bi;
                }
            }
            __syncthreads();
        }
    }
}

// ---------------- stats pass B -------------------------------------------------
__global__ void stats_kernel() {
    __shared__ float u[KCLU];
    __shared__ float sred[128];
    int tid = threadIdx.x;
    if (tid < KCLU) {
        float s = 0.0f;
        for (int b = 0; b < NBLK_PTS; b++) s += g_upart[b * KCLU + tid];
        u[tid] = s;
    }
    float sp = (tid < NBLK_PTS) ? g_Spart[tid] : 0.0f;
    sred[tid] = sp;
    __syncthreads();
    for (int s = 64; s > 0; s >>= 1) {
        if (tid < s) sred[tid] += sred[tid + s];
        __syncthreads();
    }
    if (tid == 0) {
        float S = sred[0];
        float um = 0.0f;
        for (int j = 0; j < KCLU; j++) um += u[j];
        um /= KCLU;
        float uv = 0.0f;
        for (int j = 0; j < KCLU; j++) { float d = u[j] - um; uv += d * d; }
        float usd = sqrtf(uv / (KCLU - 1));

        float v[KCLU];
        float vm = 0.0f;
        for (int j = 0; j < KCLU; j++) {
            int c = g_cnt[j]; if (c < 1) c = 1;
            v[j] = sqrtf((float)c) * S;
            vm += v[j];
        }
        vm /= KCLU;
        float vv = 0.0f;
        for (int j = 0; j < KCLU; j++) { float d = v[j] - vm; vv += d * d; }
        float vsd = sqrtf(vv / (KCLU - 1));

        float umin = 1e30f, vmin = 1e30f;
        for (int j = 0; j < KCLU; j++) {
            float un = (u[j] - um) / usd;
            float vn = (v[j] - vm) / vsd;
            u[j] = un; v[j] = vn;
            if (un < umin) umin = un;
            if (vn < vmin) vmin = vn;
        }
        for (int j = 0; j < KCLU; j++)
            g_f[j] = (u[j] - umin + 0.001f) + (v[j] - vmin + 0.001f) + 1.0f;
    }
}

// ---------------- KL pass C -----------------------------------------------------
__global__ void kl_pass() {
    __shared__ float fs[KCLU];
    __shared__ float red[256];
    int tid = threadIdx.x;
    if (tid < KCLU) fs[tid] = g_f[tid];
    __syncthreads();
    int p = blockIdx.x * 256 + tid;
    const float* qrow = g_q + (size_t)p * KCLU;
    float sw = 0.0f;
    for (int j = 0; j < KCLU; j++) { float q = qrow[j]; sw += q * q / fs[j]; }
    float inv = 1.0f / sw;
    float kl = 0.0f;
    for (int j = 0; j < KCLU; j++) {
        float q = qrow[j];
        float pj = q * q / fs[j] * inv;
        kl += pj * (logf(pj) - logf(q));
    }
    red[tid] = kl;
    __syncthreads();
    for (int s2 = 128; s2 > 0; s2 >>= 1) {
        if (tid < s2) red[tid] += red[tid + s2];
        __syncthreads();
    }
    if (tid == 0) g_klpart[blockIdx.x] = red[0];
}

// ---------------- final loss ----------------------------------------------------
__global__ void final_kernel(const float* __restrict__ clu, float* __restrict__ out) {
    __shared__ float red[256];
    int tid = threadIdx.x;
    float kl = 0.0f;
    for (int i = tid; i < NBLK_PTS; i += 256) kl += g_klpart[i];
    float re = 0.0f;
    for (int i = tid; i < NBLK_RE; i += 256) re += g_repart[i];
    float D = 0.0f;
    for (int idx = tid; idx < KCLU * KCLU; idx += 256) {
        int i = idx / KCLU, j = idx % KCLU;
        float d = 0.0f;
        for (int kk = 0; kk < NZ; kk++) {
            float t = clu[i * NZ + kk] - clu[j * NZ + kk];
            d += t * t;
        }
        D += d;
    }
    red[tid] = kl; __syncthreads();
    for (int s = 128; s > 0; s >>= 1) { if (tid < s) red[tid] += red[tid + s]; __syncthreads(); }
    float kls = red[0]; __syncthreads();
    red[tid] = re; __syncthreads();
    for (int s = 128; s > 0; s >>= 1) { if (tid < s) red[tid] += red[tid + s]; __syncthreads(); }
    float res = red[0]; __syncthreads();
    red[tid] = D; __syncthreads();
    for (int s = 128; s > 0; s >>= 1) { if (tid < s) red[tid] += red[tid + s]; __syncthreads(); }
    if (tid == 0) {
        float kl_loss = 0.01f * kls / ((float)N_PTS * (float)KCLU);
        float re_loss = res / ((float)N_PTS * 1024.0f);
        float mean_d = red[0] / (float)(KCLU * KCLU - KCLU);
        out[N_PTS] = kl_loss + re_loss + 0.01f / mean_d;
    }
}

// ---------------- host ----------------------------------------------------------
extern "C" void kernel_launch(void* const* d_in, const int* in_sizes, int n_in,
                              void* d_out, int out_size) {
    const float* x   = (const float*)d_in[0];
    const float* t1  = (const float*)d_in[1];
    const float* clu = (const float*)d_in[2];
    const float* We1 = (const float*)d_in[3];  const float* be1 = (const float*)d_in[4];
    const float* We2 = (const float*)d_in[5];  const float* be2 = (const float*)d_in[6];
    const float* We3 = (const float*)d_in[7];  const float* be3 = (const float*)d_in[8];
    const float* Wz  = (const float*)d_in[9];  const float* bz  = (const float*)d_in[10];
    const float* Wd1 = (const float*)d_in[11]; const float* bd1 = (const float*)d_in[12];
    const float* Wd2 = (const float*)d_in[13]; const float* bd2 = (const float*)d_in[14];
    const float* Wd3 = (const float*)d_in[15]; const float* bd3 = (const float*)d_in[16];
    const float* Wxb = (const float*)d_in[17]; const float* bxb = (const float*)d_in[18];
    float* out = (float*)d_out;

    float *P, *h1, *h2, *zb, *wt, *repart;
    cudaGetSymbolAddress((void**)&P,  g_P);
    cudaGetSymbolAddress((void**)&h1, g_h1);
    cudaGetSymbolAddress((void**)&h2, g_h2);
    cudaGetSymbolAddress((void**)&zb, g_z);
    cudaGetSymbolAddress((void**)&wt, g_wt);
    cudaGetSymbolAddress((void**)&repart, g_repart);

    constexpr int SM_ENC = 2 * 2 * (128 * 36 + 128 * 36) * 4;   // 147456 B
    constexpr int SM_Z   = 2 * 2 * (128 * 36 + 32 * 36) * 4;    //  92160 B
    constexpr int SM_DEC = 2 * 1 * (128 * 36 + 128 * 36) * 4;   //  73728 B
    constexpr int SM_RES = (RB * 1024 + RB * 2048 + RB * 512 + RB * 512 + RB * 32 + 128) * 4;
    cudaFuncSetAttribute(mma_gemm<128, 2, 0>, cudaFuncAttributeMaxDynamicSharedMemorySize, SM_ENC);
    cudaFuncSetAttribute(mma_gemm<32, 2, 1>,  cudaFuncAttributeMaxDynamicSharedMemorySize, SM_Z);
    cudaFuncSetAttribute(mma_gemm<128, 1, 0>, cudaFuncAttributeMaxDynamicSharedMemorySize, SM_DEC);
    cudaFuncSetAttribute(mma_gemm<128, 1, 2>, cudaFuncAttributeMaxDynamicSharedMemorySize, SM_DEC);
    cudaFuncSetAttribute(rescue_kernel, cudaFuncAttributeMaxDynamicSharedMemorySize, SM_RES);

    init_kernel<<<1, 128>>>();

    const dim3 blk(256);
    const int MB = N_PTS / 128;  // 232
    dim3 tb(32, 8);

    // encoder (3xTF32 split)
    transpose_w<<<dim3(512 / 32, 1024 / 32), tb>>>(We1, wt, 1024, 512);
    mma_gemm<128, 2, 0><<<dim3(4, MB), blk, SM_ENC>>>(x, wt, be1, h1, nullptr, nullptr, 512, 1024);
    transpose_w<<<dim3(512 / 32, 512 / 32), tb>>>(We2, wt, 512, 512);
    mma_gemm<128, 2, 0><<<dim3(4, MB), blk, SM_ENC>>>(h1, wt, be2, h2, nullptr, nullptr, 512, 512);
    transpose_w<<<dim3(2048 / 32, 512 / 32), tb>>>(We3, wt, 512, 2048);
    mma_gemm<128, 2, 0><<<dim3(16, MB), blk, SM_ENC>>>(h2, wt, be3, P, nullptr, nullptr, 2048, 512);
    transpose_w<<<dim3(1, 2048 / 32), tb>>>(Wz, wt, 2048, 32);
    mma_gemm<32, 2, 1><<<dim3(1, MB), blk, SM_Z>>>(P, wt, bz, zb, nullptr, nullptr, 32, 2048);
    // decoder (single-pass tf32)
    transpose_w<<<dim3(2048 / 32, 1), tb>>>(Wd1, wt, 32, 2048);
    mma_gemm<128, 1, 0><<<dim3(16, MB), blk, SM_DEC>>>(zb, wt, bd1, P, nullptr, nullptr, 2048, 32);
    transpose_w<<<dim3(512 / 32, 2048 / 32), tb>>>(Wd2, wt, 2048, 512);
    mma_gemm<128, 1, 0><<<dim3(4, MB), blk, SM_DEC>>>(P, wt, bd2, h1, nullptr, nullptr, 512, 2048);
    transpose_w<<<dim3(512 / 32, 512 / 32), tb>>>(Wd3, wt, 512, 512);
    mma_gemm<128, 1, 0><<<dim3(4, MB), blk, SM_DEC>>>(h1, wt, bd3, h2, nullptr, nullptr, 512, 512);
    transpose_w<<<dim3(1024 / 32, 512 / 32), tb>>>(Wxb, wt, 512, 1024);
    mma_gemm<128, 1, 2><<<dim3(8, MB), blk, SM_DEC>>>(h2, wt, bxb, nullptr, x, repart, 1024, 512);

    // clustering + rescue + loss
    cluster_pass<<<NBLK_PTS, 256>>>(t1, clu, out);
    rescue_kernel<<<128, 256, SM_RES>>>(x, t1, clu, We1, be1, We2, be2, We3, be3, Wz, bz, out);
    stats_kernel<<<1, 128>>>();
    kl_pass<<<NBLK_PTS, 256>>>();
    final_kernel<<<1, 256>>>(clu, out);

    int extra = out_size - (N_PTS + 1);
    if (extra > 0) fill_zero_kernel<<<(extra + 255) / 256, 256>>>(out + N_PTS + 1, extra);
}

// round 7
// speedup vs baseline: 1.6976x; 1.0105x over previous
#include <cuda_runtime.h>
#include <math.h>
#include <stdint.h>

#define N_PTS   29696
#define NZ      32
#define KCLU    100
#define EPSF    1e-5f
#define INDEXF  29696.0f
#define NBLK_PTS 116          // N_PTS / 256
#define NBLK_RE  1856         // (1024/128) * (29696/128)
#define GAP_TAU 3e-4f

// ---------------- scratch (static device globals; no allocation) -------------
__device__ float g_P [(size_t)N_PTS * 2048];   // h3, then d1
__device__ float g_h1[(size_t)N_PTS * 512];    // h1, then d2
__device__ float g_h2[(size_t)N_PTS * 512];    // h2, then d3
__device__ float g_z [(size_t)N_PTS * NZ];
__device__ float g_q [(size_t)N_PTS * KCLU];
__device__ float g_wt[2048 * 512];             // transposed weights (reused per layer)
__device__ float g_upart[NBLK_PTS * KCLU];
__device__ float g_Spart[NBLK_PTS];
__device__ float g_klpart[NBLK_PTS];
__device__ float g_repart[NBLK_RE];
__device__ int   g_cnt[KCLU];
__device__ float g_f[KCLU];
__device__ int   g_nflag;
__device__ int   g_flaglist[N_PTS];

// ---------------- helpers ------------------------------------------------------
__device__ __forceinline__ float tf32_rna(float x) {
    uint32_t u;
    asm("cvt.rna.tf32.f32 %0, %1;" : "=r"(u) : "f"(x));
    return __uint_as_float(u);
}
__device__ __forceinline__ uint32_t smem_u32(const void* p) {
    uint32_t a;
    asm("{ .reg .u64 t; cvta.to.shared.u64 t, %1; cvt.u32.u64 %0, t; }" : "=r"(a) : "l"(p));
    return a;
}
__device__ __forceinline__ void cp_async16(uint32_t s, const void* g) {
    asm volatile("cp.async.cg.shared.global [%0], [%1], 16;" :: "r"(s), "l"(g));
}
#define CP_COMMIT() asm volatile("cp.async.commit_group;" ::: "memory")
#define CP_WAIT1()  asm volatile("cp.async.wait_group 1;" ::: "memory")
#define MMA_TF32(c, a, b) \
    asm volatile("mma.sync.aligned.m16n8k8.row.col.f32.tf32.tf32.f32 " \
        "{%0,%1,%2,%3}, {%4,%5,%6,%7}, {%8,%9}, {%0,%1,%2,%3};" \
        : "+f"((c)[0]), "+f"((c)[1]), "+f"((c)[2]), "+f"((c)[3]) \
        : "r"((a)[0]), "r"((a)[1]), "r"((a)[2]), "r"((a)[3]), \
          "r"((b)[0]), "r"((b)[1]))

__global__ void init_kernel() {
    int tid = threadIdx.x;
    if (tid < KCLU) g_cnt[tid] = 0;
    if (tid == 0) g_nflag = 0;
}
__global__ void fill_zero_kernel(float* p, int n) {
    int i = blockIdx.x * blockDim.x + threadIdx.x;
    if (i < n) p[i] = 0.0f;
}
// Wt[n,k] = W[k,n]; dims multiples of 32. grid(Nd/32, Kd/32), block(32,8)
__global__ void transpose_w(const float* __restrict__ in, float* __restrict__ out,
                            int Kd, int Nd) {
    __shared__ float t[32][33];
    int n0 = blockIdx.x * 32, k0 = blockIdx.y * 32;
    int tx = threadIdx.x, ty = threadIdx.y;
    for (int i = ty; i < 32; i += 8) t[i][tx] = in[(size_t)(k0 + i) * Nd + n0 + tx];
    __syncthreads();
    for (int i = ty; i < 32; i += 8) out[(size_t)(n0 + i) * Kd + k0 + tx] = t[tx][i];
}

// ---------------- tf32 mma.sync GEMM (cp.async, register-split) ----------------
// C[M,N] = epi(A[M,K] @ Wt[N,K]^T + bias).
// NT=2: 3xTF32 Dekker split (done in registers). NT=1: single tf32 pass.
// EPI: 0 relu-store, 1 plain store, 2 fused sum((v-X)^2) block partials.
// Block 256 thr = 8 warps (2x4); block tile 128 x BN; warp tile 64 x BN/4.
template <int BN, int NT, int EPI>
__global__ void __launch_bounds__(256, 2)
mma_gemm(const float* __restrict__ A, const float* __restrict__ Bt,
         const float* __restrict__ bias, float* __restrict__ C,
         const float* __restrict__ X, float* __restrict__ part,
         int N, int K) {
    extern __shared__ float smf[];
    constexpr int LDA = 36;                 // floats; conflict-free frags + 16B stores
    constexpr int A_TILE_F = 128 * LDA;
    constexpr int B_TILE_F = BN * LDA;
    constexpr int STAGE_F = A_TILE_F + B_TILE_F;   // raw fp32, single copy
    constexpr int NTL = BN / 32;
    constexpr int WN = BN / 4;
    constexpr int B_CP = (BN * 8) / 256;    // 16B chunks per thread for B

    const int tid = threadIdx.x;
    const int wid = tid >> 5;
    const int lane = tid & 31;
    const int g = lane >> 2;
    const int t = lane & 3;
    const int warp_m = wid >> 2;
    const int warp_n = wid & 3;
    const int bm = blockIdx.y * 128, bn = blockIdx.x * BN;
    const uint32_t sb = smem_u32(smf);

    float acc[4][NTL][4];
#pragma unroll
    for (int mt = 0; mt < 4; mt++)
#pragma unroll
        for (int nt = 0; nt < NTL; nt++)
#pragma unroll
            for (int i = 0; i < 4; i++) acc[mt][nt][i] = 0.0f;

    const int NC = K >> 5;

    auto prefetch = [&](int c, int s) {
        const int k0 = c << 5;
        const uint32_t base = sb + (uint32_t)s * STAGE_F * 4;
#pragma unroll
        for (int i = 0; i < 4; i++) {
            int idx = tid + i * 256;
            int r = idx >> 3, c4 = idx & 7;
            cp_async16(base + (r * LDA + c4 * 4) * 4,
                       &A[(size_t)(bm + r) * K + k0 + c4 * 4]);
        }
#pragma unroll
        for (int i = 0; i < B_CP; i++) {
            int idx = tid + i * 256;
            int r = idx >> 3, c4 = idx & 7;
            cp_async16(base + (A_TILE_F + r * LDA + c4 * 4) * 4,
                       &Bt[(size_t)(bn + r) * K + k0 + c4 * 4]);
        }
    };

    auto compute = [&](int s) {
        const float* As = smf + s * STAGE_F;
        const float* Bs = As + A_TILE_F;
#pragma unroll
        for (int ks = 0; ks < 4; ks++) {
            const int kk = ks * 8 + t;
            uint32_t bh[NTL][2], bl[NTL][2];
#pragma unroll
            for (int nt = 0; nt < NTL; nt++) {
                int nb = warp_n * WN + nt * 8 + g;
                float v0 = Bs[nb * LDA + kk];
                float v1 = Bs[nb * LDA + kk + 4];
                float h0 = tf32_rna(v0), h1 = tf32_rna(v1);
                bh[nt][0] = __float_as_uint(h0);
                bh[nt][1] = __float_as_uint(h1);
                if (NT == 2) {
                    bl[nt][0] = __float_as_uint(tf32_rna(v0 - h0));
                    bl[nt][1] = __float_as_uint(tf32_rna(v1 - h1));
                }
            }
#pragma unroll
            for (int mt = 0; mt < 4; mt++) {
                int mb = warp_m * 64 + mt * 16 + g;
                float a0 = As[mb * LDA + kk];
                float a1 = As[(mb + 8) * LDA + kk];
                float a2 = As[mb * LDA + kk + 4];
                float a3 = As[(mb + 8) * LDA + kk + 4];
                float h0 = tf32_rna(a0), h1 = tf32_rna(a1);
                float h2 = tf32_rna(a2), h3 = tf32_rna(a3);
                uint32_t ah[4];
                ah[0] = __float_as_uint(h0); ah[1] = __float_as_uint(h1);
                ah[2] = __float_as_uint(h2); ah[3] = __float_as_uint(h3);
#pragma unroll
                for (int nt = 0; nt < NTL; nt++) MMA_TF32(acc[mt][nt], ah, bh[nt]);
                if (NT == 2) {
                    uint32_t al[4];
                    al[0] = __float_as_uint(tf32_rna(a0 - h0));
                    al[1] = __float_as_uint(tf32_rna(a1 - h1));
                    al[2] = __float_as_uint(tf32_rna(a2 - h2));
                    al[3] = __float_as_uint(tf32_rna(a3 - h3));
#pragma unroll
                    for (int nt = 0; nt < NTL; nt++) {
                        MMA_TF32(acc[mt][nt], ah, bl[nt]);
                        MMA_TF32(acc[mt][nt], al, bh[nt]);
                    }
                }
            }
        }
    };

    // ---- pipelined mainloop (2-stage cp.async) ----
    prefetch(0, 0);
    CP_COMMIT();
    if (NC > 1) prefetch(1, 1);
    CP_COMMIT();
    CP_WAIT1();
    __syncthreads();
#pragma unroll 1
    for (int c = 0; c < NC; c++) {
        compute(c & 1);
        __syncthreads();                       // all warps done reading stage c&1
        if (c + 2 < NC) prefetch(c + 2, c & 1);
        CP_COMMIT();
        CP_WAIT1();                            // stage (c+1)&1 ready
        __syncthreads();
    }

    // ---- epilogue straight from accumulators ----
    float lsum = 0.0f;
#pragma unroll
    for (int mt = 0; mt < 4; mt++) {
#pragma unroll
        for (int nt = 0; nt < NTL; nt++) {
            int row = bm + warp_m * 64 + mt * 16 + g;
            int col = bn + warp_n * WN + nt * 8 + 2 * t;
            float b0 = bias[col], b1 = bias[col + 1];
            float v0 = acc[mt][nt][0] + b0, v1 = acc[mt][nt][1] + b1;
            float v2 = acc[mt][nt][2] + b0, v3 = acc[mt][nt][3] + b1;
            if (EPI == 0) {
                v0 = fmaxf(v0, 0.0f); v1 = fmaxf(v1, 0.0f);
                v2 = fmaxf(v2, 0.0f); v3 = fmaxf(v3, 0.0f);
            }
            size_t i0 = (size_t)row * N + col;
            size_t i1 = (size_t)(row + 8) * N + col;
            if (EPI == 2) {
                float2 x0 = *reinterpret_cast<const float2*>(&X[i0]);
                float2 x1 = *reinterpret_cast<const float2*>(&X[i1]);
                float d0 = v0 - x0.x, d1 = v1 - x0.y, d2 = v2 - x1.x, d3 = v3 - x1.y;
                lsum += d0 * d0 + d1 * d1 + d2 * d2 + d3 * d3;
            } else {
                float2 o0 = make_float2(v0, v1), o1 = make_float2(v2, v3);
                *reinterpret_cast<float2*>(&C[i0]) = o0;
                *reinterpret_cast<float2*>(&C[i1]) = o1;
            }
        }
    }
    if (EPI == 2) {
        __syncthreads();
        smf[tid] = lsum;
        __syncthreads();
        for (int s2 = 128; s2 > 0; s2 >>= 1) {
            if (tid < s2) smf[tid] += smf[tid + s2];
            __syncthreads();
        }
        if (tid == 0) part[blockIdx.y * gridDim.x + blockIdx.x] = smf[0];
    }
}

// ---------------- clustering pass A -------------------------------------------
__global__ void cluster_pass(const float* __restrict__ t1,
                             const float* __restrict__ clu,
                             float* __restrict__ out_predict) {
    __shared__ float cs[KCLU * NZ];
    __shared__ float u_s[KCLU];
    __shared__ float red[256];
    int tid = threadIdx.x;
    for (int i = tid; i < KCLU * NZ; i += 256) cs[i] = clu[i];
    if (tid < KCLU) u_s[tid] = 0.0f;
    __syncthreads();

    int p = blockIdx.x * 256 + tid;
    float zr[NZ];
    const float* zp = g_z + (size_t)p * NZ;
#pragma unroll
    for (int i = 0; i < NZ; i++) zr[i] = zp[i];

    float cm = (t1[p * 3 + 0] * 0.01f) * (t1[p * 3 + 1] * 0.01f) * (t1[p * 3 + 2] * 0.01f)
               * 0.99f + 1.0f;
    float s = 0.0f;
#pragma unroll
    for (int i = 0; i < NZ; i++) { zr[i] *= cm; s += zr[i]; }
    float mean = s * (1.0f / NZ);
    float var = 0.0f;
#pragma unroll
    for (int i = 0; i < NZ; i++) { float d = zr[i] - mean; var += d * d; }
    float isd = 1.0f / sqrtf(var * (1.0f / (NZ - 1)));
#pragma unroll
    for (int i = 0; i < NZ; i++) zr[i] = (zr[i] - mean) * isd;

    float sumq = 0.0f, best = -1.0f, best2 = -1.0f;
    int bi = 0;
    for (int j = 0; j < KCLU; j++) {
        const float* c = &cs[j * NZ];
        float d = 0.0f;
#pragma unroll
        for (int i = 0; i < NZ; i++) { float tt = zr[i] - c[i]; d += tt * tt; }
        float qu = EPSF + d;
        sumq += qu;
        if (qu > best) { best2 = best; best = qu; bi = j; }
        else if (qu > best2) best2 = qu;
    }
    out_predict[p] = (float)bi;
    atomicAdd(&g_cnt[bi], 1);
    if (best - best2 < GAP_TAU * best) {       // near-tie: flag for fp32 rescue
        int ii = atomicAdd(&g_nflag, 1);
        g_flaglist[ii] = p;
    }

    float inv = 1.0f / sumq;
    float Sl = 0.0f;
    float* qrow = g_q + (size_t)p * KCLU;
    for (int j = 0; j < KCLU; j++) {
        const float* c = &cs[j * NZ];
        float d = 0.0f;
#pragma unroll
        for (int i = 0; i < NZ; i++) { float tt = zr[i] - c[i]; d += tt * tt; }
        float qn = (EPSF + d) * inv;
        qrow[j] = qn;
        atomicAdd(&u_s[j], qn);
        float lq = logf(qn);
        float tq = (1.0f - qn) * (1.0f - qn) * lq * INDEXF;
        Sl += sqrtf(-1.0f / tq);
    }

    red[tid] = Sl;
    __syncthreads();
    for (int s2 = 128; s2 > 0; s2 >>= 1) {
        if (tid < s2) red[tid] += red[tid + s2];
        __syncthreads();
    }
    if (tid == 0) g_Spart[blockIdx.x] = red[0];
    __syncthreads();
    if (tid < KCLU) g_upart[blockIdx.x * KCLU + tid] = u_s[tid];
}

// ---------------- fp32 rescue for near-tie points ------------------------------
#define RB 8
__global__ void __launch_bounds__(256, 1)
rescue_kernel(const float* __restrict__ x, const float* __restrict__ t1,
              const float* __restrict__ clu,
              const float* __restrict__ We1, const float* __restrict__ be1,
              const float* __restrict__ We2, const float* __restrict__ be2,
              const float* __restrict__ We3, const float* __restrict__ be3,
              const float* __restrict__ Wz,  const float* __restrict__ bz,
              float* __restrict__ out_predict) {
    extern __shared__ float sm[];
    float* xb  = sm;                 // RB*1024
    float* hh  = xb + RB * 1024;     // RB*2048
    float* s1b = hh + RB * 2048;     // RB*512
    float* s2b = s1b + RB * 512;     // RB*512
    float* zz  = s2b + RB * 512;     // RB*32
    float* dst = zz + RB * 32;       // 128
    const int tid = threadIdx.x;
    const int nf = g_nflag;

    for (int base = blockIdx.x * RB; base < nf; base += gridDim.x * RB) {
        const int cb = min(RB, nf - base);
        __syncthreads();
        for (int i = 0; i < RB; i++) {
            int p = g_flaglist[base + (i < cb ? i : 0)];
            for (int k = tid; k < 1024; k += 256)
                xb[i * 1024 + k] = x[(size_t)p * 1024 + k];
        }
        __syncthreads();
        for (int n = tid; n < 512; n += 256) {
            float acc[RB] = {};
            for (int k = 0; k < 1024; k++) {
                float w = We1[(size_t)k * 512 + n];
#pragma unroll
                for (int i = 0; i < RB; i++) acc[i] += xb[i * 1024 + k] * w;
            }
            float b = be1[n];
#pragma unroll
            for (int i = 0; i < RB; i++) s1b[i * 512 + n] = fmaxf(acc[i] + b, 0.0f);
        }
        __syncthreads();
        for (int n = tid; n < 512; n += 256) {
            float acc[RB] = {};
            for (int k = 0; k < 512; k++) {
                float w = We2[(size_t)k * 512 + n];
#pragma unroll
                for (int i = 0; i < RB; i++) acc[i] += s1b[i * 512 + k] * w;
            }
            float b = be2[n];
#pragma unroll
            for (int i = 0; i < RB; i++) s2b[i * 512 + n] = fmaxf(acc[i] + b, 0.0f);
        }
        __syncthreads();
        for (int n = tid; n < 2048; n += 256) {
            float acc[RB] = {};
            for (int k = 0; k < 512; k++) {
                float w = We3[(size_t)k * 2048 + n];
#pragma unroll
                for (int i = 0; i < RB; i++) acc[i] += s2b[i * 512 + k] * w;
            }
            float b = be3[n];
#pragma unroll
            for (int i = 0; i < RB; i++) hh[i * 2048 + n] = fmaxf(acc[i] + b, 0.0f);
        }
        __syncthreads();
        if (tid < 32) {
            int n = tid;
            float acc[RB] = {};
            for (int k = 0; k < 2048; k++) {
                float w = Wz[(size_t)k * 32 + n];
#pragma unroll
                for (int i = 0; i < RB; i++) acc[i] += hh[i * 2048 + k] * w;
            }
            float b = bz[n];
#pragma unroll
            for (int i = 0; i < RB; i++) zz[i * 32 + n] = acc[i] + b;
        }
        __syncthreads();
        if (tid < cb) {
            int i = tid;
            int p = g_flaglist[base + i];
            float cm = (t1[p * 3 + 0] * 0.01f) * (t1[p * 3 + 1] * 0.01f) *
                       (t1[p * 3 + 2] * 0.01f) * 0.99f + 1.0f;
            float s = 0.0f;
            for (int k = 0; k < NZ; k++) { zz[i * 32 + k] *= cm; s += zz[i * 32 + k]; }
            float mean = s * (1.0f / NZ);
            float var = 0.0f;
            for (int k = 0; k < NZ; k++) {
                float d = zz[i * 32 + k] - mean; var += d * d;
            }
            float isd = 1.0f / sqrtf(var * (1.0f / (NZ - 1)));
            for (int k = 0; k < NZ; k++) zz[i * 32 + k] = (zz[i * 32 + k] - mean) * isd;
        }
        __syncthreads();
        for (int i = 0; i < cb; i++) {
            if (tid < KCLU) {
                float d = 0.0f;
                for (int k = 0; k < NZ; k++) {
                    float tt = zz[i * 32 + k] - clu[tid * NZ + k];
                    d += tt * tt;
                }
                dst[tid] = d;
            }
            __syncthreads();
            if (tid == 0) {
                float best = -1.0f; int bi = 0;
                for (int j = 0; j < KCLU; j++)
                    if (dst[j] > best) { best = dst[j]; bi = j; }
                int p = g_flaglist[base + i];
                int old = (int)out_predict[p];
                if (old != bi) {
                    atomicAdd(&g_cnt[old], -1);
                    atomicAdd(&g_cnt[bi], 1);
                    out_predict[p] = (float)bi;
                }
            }
            __syncthreads();
        }
    }
}

// ---------------- stats pass B -------------------------------------------------
__global__ void stats_kernel() {
    __shared__ float u[KCLU];
    __shared__ float sred[128];
    int tid = threadIdx.x;
    if (tid < KCLU) {
        float s = 0.0f;
        for (int b = 0; b < NBLK_PTS; b++) s += g_upart[b * KCLU + tid];
        u[tid] = s;
    }
    float sp = (tid < NBLK_PTS) ? g_Spart[tid] : 0.0f;
    sred[tid] = sp;
    __syncthreads();
    for (int s = 64; s > 0; s >>= 1) {
        if (tid < s) sred[tid] += sred[tid + s];
        __syncthreads();
    }
    if (tid == 0) {
        float S = sred[0];
        float um = 0.0f;
        for (int j = 0; j < KCLU; j++) um += u[j];
        um /= KCLU;
        float uv = 0.0f;
        for (int j = 0; j < KCLU; j++) { float d = u[j] - um; uv += d * d; }
        float usd = sqrtf(uv / (KCLU - 1));

        float v[KCLU];
        float vm = 0.0f;
        for (int j = 0; j < KCLU; j++) {
            int c = g_cnt[j]; if (c < 1) c = 1;
            v[j] = sqrtf((float)c) * S;
            vm += v[j];
        }
        vm /= KCLU;
        float vv = 0.0f;
        for (int j = 0; j < KCLU; j++) { float d = v[j] - vm; vv += d * d; }
        float vsd = sqrtf(vv / (KCLU - 1));

        float umin = 1e30f, vmin = 1e30f;
        for (int j = 0; j < KCLU; j++) {
            float un = (u[j] - um) / usd;
            float vn = (v[j] - vm) / vsd;
            u[j] = un; v[j] = vn;
            if (un < umin) umin = un;
            if (vn < vmin) vmin = vn;
        }
        for (int j = 0; j < KCLU; j++)
            g_f[j] = (u[j] - umin + 0.001f) + (v[j] - vmin + 0.001f) + 1.0f;
    }
}

// ---------------- KL pass C -----------------------------------------------------
__global__ void kl_pass() {
    __shared__ float fs[KCLU];
    __shared__ float red[256];
    int tid = threadIdx.x;
    if (tid < KCLU) fs[tid] = g_f[tid];
    __syncthreads();
    int p = blockIdx.x * 256 + tid;
    const float* qrow = g_q + (size_t)p * KCLU;
    float sw = 0.0f;
    for (int j = 0; j < KCLU; j++) { float q = qrow[j]; sw += q * q / fs[j]; }
    float inv = 1.0f / sw;
    float kl = 0.0f;
    for (int j = 0; j < KCLU; j++) {
        float q = qrow[j];
        float pj = q * q / fs[j] * inv;
        kl += pj * (logf(pj) - logf(q));
    }
    red[tid] = kl;
    __syncthreads();
    for (int s2 = 128; s2 > 0; s2 >>= 1) {
        if (tid < s2) red[tid] += red[tid + s2];
        __syncthreads();
    }
    if (tid == 0) g_klpart[blockIdx.x] = red[0];
}

// ---------------- final loss ----------------------------------------------------
__global__ void final_kernel(const float* __restrict__ clu, float* __restrict__ out) {
    __shared__ float red[256];
    int tid = threadIdx.x;
    float kl = 0.0f;
    for (int i = tid; i < NBLK_PTS; i += 256) kl += g_klpart[i];
    float re = 0.0f;
    for (int i = tid; i < NBLK_RE; i += 256) re += g_repart[i];
    float D = 0.0f;
    for (int idx = tid; idx < KCLU * KCLU; idx += 256) {
        int i = idx / KCLU, j = idx % KCLU;
        float d = 0.0f;
        for (int kk = 0; kk < NZ; kk++) {
            float t = clu[i * NZ + kk] - clu[j * NZ + kk];
            d += t * t;
        }
        D += d;
    }
    red[tid] = kl; __syncthreads();
    for (int s = 128; s > 0; s >>= 1) { if (tid < s) red[tid] += red[tid + s]; __syncthreads(); }
    float kls = red[0]; __syncthreads();
    red[tid] = re; __syncthreads();
    for (int s = 128; s > 0; s >>= 1) { if (tid < s) red[tid] += red[tid + s]; __syncthreads(); }
    float res = red[0]; __syncthreads();
    red[tid] = D; __syncthreads();
    for (int s = 128; s > 0; s >>= 1) { if (tid < s) red[tid] += red[tid + s]; __syncthreads(); }
    if (tid == 0) {
        float kl_loss = 0.01f * kls / ((float)N_PTS * (float)KCLU);
        float re_loss = res / ((float)N_PTS * 1024.0f);
        float mean_d = red[0] / (float)(KCLU * KCLU - KCLU);
        out[N_PTS] = kl_loss + re_loss + 0.01f / mean_d;
    }
}

// ---------------- host ----------------------------------------------------------
extern "C" void kernel_launch(void* const* d_in, const int* in_sizes, int n_in,
                              void* d_out, int out_size) {
    const float* x   = (const float*)d_in[0];
    const float* t1  = (const float*)d_in[1];
    const float* clu = (const float*)d_in[2];
    const float* We1 = (const float*)d_in[3];  const float* be1 = (const float*)d_in[4];
    const float* We2 = (const float*)d_in[5];  const float* be2 = (const float*)d_in[6];
    const float* We3 = (const float*)d_in[7];  const float* be3 = (const float*)d_in[8];
    const float* Wz  = (const float*)d_in[9];  const float* bz  = (const float*)d_in[10];
    const float* Wd1 = (const float*)d_in[11]; const float* bd1 = (const float*)d_in[12];
    const float* Wd2 = (const float*)d_in[13]; const float* bd2 = (const float*)d_in[14];
    const float* Wd3 = (const float*)d_in[15]; const float* bd3 = (const float*)d_in[16];
    const float* Wxb = (const float*)d_in[17]; const float* bxb = (const float*)d_in[18];
    float* out = (float*)d_out;

    float *P, *h1, *h2, *zb, *wt, *repart;
    cudaGetSymbolAddress((void**)&P,  g_P);
    cudaGetSymbolAddress((void**)&h1, g_h1);
    cudaGetSymbolAddress((void**)&h2, g_h2);
    cudaGetSymbolAddress((void**)&zb, g_z);
    cudaGetSymbolAddress((void**)&wt, g_wt);
    cudaGetSymbolAddress((void**)&repart, g_repart);

    constexpr int SM_128 = 2 * (128 * 36 + 128 * 36) * 4;   // 73728 B
    constexpr int SM_32  = 2 * (128 * 36 + 32 * 36) * 4;    // 46080 B
    constexpr int SM_RES = (RB * 1024 + RB * 2048 + RB * 512 + RB * 512 + RB * 32 + 128) * 4;
    cudaFuncSetAttribute(mma_gemm<128, 2, 0>, cudaFuncAttributeMaxDynamicSharedMemorySize, SM_128);
    cudaFuncSetAttribute(mma_gemm<32, 2, 1>,  cudaFuncAttributeMaxDynamicSharedMemorySize, SM_32);
    cudaFuncSetAttribute(mma_gemm<128, 1, 0>, cudaFuncAttributeMaxDynamicSharedMemorySize, SM_128);
    cudaFuncSetAttribute(mma_gemm<128, 1, 2>, cudaFuncAttributeMaxDynamicSharedMemorySize, SM_128);
    cudaFuncSetAttribute(rescue_kernel, cudaFuncAttributeMaxDynamicSharedMemorySize, SM_RES);

    init_kernel<<<1, 128>>>();

    const dim3 blk(256);
    const int MB = N_PTS / 128;  // 232
    dim3 tb(32, 8);

    // encoder (3xTF32 split)
    transpose_w<<<dim3(512 / 32, 1024 / 32), tb>>>(We1, wt, 1024, 512);
    mma_gemm<128, 2, 0><<<dim3(4, MB), blk, SM_128>>>(x, wt, be1, h1, nullptr, nullptr, 512, 1024);
    transpose_w<<<dim3(512 / 32, 512 / 32), tb>>>(We2, wt, 512, 512);
    mma_gemm<128, 2, 0><<<dim3(4, MB), blk, SM_128>>>(h1, wt, be2, h2, nullptr, nullptr, 512, 512);
    transpose_w<<<dim3(2048 / 32, 512 / 32), tb>>>(We3, wt, 512, 2048);
    mma_gemm<128, 2, 0><<<dim3(16, MB), blk, SM_128>>>(h2, wt, be3, P, nullptr, nullptr, 2048, 512);
    transpose_w<<<dim3(1, 2048 / 32), tb>>>(Wz, wt, 2048, 32);
    mma_gemm<32, 2, 1><<<dim3(1, MB), blk, SM_32>>>(P, wt, bz, zb, nullptr, nullptr, 32, 2048);
    // decoder (single-pass tf32)
    transpose_w<<<dim3(2048 / 32, 1), tb>>>(Wd1, wt, 32, 2048);
    mma_gemm<128, 1, 0><<<dim3(16, MB), blk, SM_128>>>(zb, wt, bd1, P, nullptr, nullptr, 2048, 32);
    transpose_w<<<dim3(512 / 32, 2048 / 32), tb>>>(Wd2, wt, 2048, 512);
    mma_gemm<128, 1, 0><<<dim3(4, MB), blk, SM_128>>>(P, wt, bd2, h1, nullptr, nullptr, 512, 2048);
    transpose_w<<<dim3(512 / 32, 512 / 32), tb>>>(Wd3, wt, 512, 512);
    mma_gemm<128, 1, 0><<<dim3(4, MB), blk, SM_128>>>(h1, wt, bd3, h2, nullptr, nullptr, 512, 512);
    transpose_w<<<dim3(1024 / 32, 512 / 32), tb>>>(Wxb, wt, 512, 1024);
    mma_gemm<128, 1, 2><<<dim3(8, MB), blk, SM_128>>>(h2, wt, bxb, nullptr, x, repart, 1024, 512);

    // clustering + rescue + loss
    cluster_pass<<<NBLK_PTS, 256>>>(t1, clu, out);
    rescue_kernel<<<128, 256, SM_RES>>>(x, t1, clu, We1, be1, We2, be2, We3, be3, Wz, bz, out);
    stats_kernel<<<1, 128>>>();
    kl_pass<<<NBLK_PTS, 256>>>();
    final_kernel<<<1, 256>>>(clu, out);

    int extra = out_size - (N_PTS + 1);
    if (extra > 0) fill_zero_kernel<<<(extra + 255) / 256, 256>>>(out + N_PTS + 1, extra);
}

// round 8
// speedup vs baseline: 2.1509x; 1.2670x over previous
#include <cuda_runtime.h>
#include <math.h>
#include <stdint.h>

#define N_PTS   29696
#define NZ      32
#define KCLU    100
#define EPSF    1e-5f
#define INDEXF  29696.0f
#define NBLK_PTS 116          // N_PTS / 256
#define NBLK_RE  1856         // (1024/128) * (29696/128)
#define GAP_TAU 5e-3f

// ---------------- scratch (static device globals; no allocation) -------------
__device__ float g_P [(size_t)N_PTS * 2048];   // h3, then d1
__device__ float g_h1[(size_t)N_PTS * 512];    // h1, then d2
__device__ float g_h2[(size_t)N_PTS * 512];    // h2, then d3
__device__ float g_z [(size_t)N_PTS * NZ];
__device__ float g_q [(size_t)N_PTS * KCLU];
__device__ float g_upart[NBLK_PTS * KCLU];
__device__ float g_Spart[NBLK_PTS];
__device__ float g_klpart[NBLK_PTS];
__device__ float g_repart[NBLK_RE];
__device__ int   g_cnt[KCLU];
__device__ float g_f[KCLU];
__device__ int   g_nflag;
__device__ int   g_flaglist[N_PTS];

// ---------------- helpers ------------------------------------------------------
__device__ __forceinline__ float tf32_rna(float x) {
    uint32_t u;
    asm("cvt.rna.tf32.f32 %0, %1;" : "=r"(u) : "f"(x));
    return __uint_as_float(u);
}
__device__ __forceinline__ uint32_t smem_u32(const void* p) {
    uint32_t a;
    asm("{ .reg .u64 t; cvta.to.shared.u64 t, %1; cvt.u32.u64 %0, t; }" : "=r"(a) : "l"(p));
    return a;
}
__device__ __forceinline__ void cp_async16(uint32_t s, const void* g) {
    asm volatile("cp.async.cg.shared.global [%0], [%1], 16;" :: "r"(s), "l"(g));
}
#define CP_COMMIT() asm volatile("cp.async.commit_group;" ::: "memory")
#define CP_WAIT1()  asm volatile("cp.async.wait_group 1;" ::: "memory")
#define CP_WAIT0()  asm volatile("cp.async.wait_group 0;" ::: "memory")
#define MMA_TF32(c, a, b) \
    asm volatile("mma.sync.aligned.m16n8k8.row.col.f32.tf32.tf32.f32 " \
        "{%0,%1,%2,%3}, {%4,%5,%6,%7}, {%8,%9}, {%0,%1,%2,%3};" \
        : "+f"((c)[0]), "+f"((c)[1]), "+f"((c)[2]), "+f"((c)[3]) \
        : "r"((a)[0]), "r"((a)[1]), "r"((a)[2]), "r"((a)[3]), \
          "r"((b)[0]), "r"((b)[1]))

__global__ void init_kernel() {
    int tid = threadIdx.x;
    if (tid < KCLU) g_cnt[tid] = 0;
    if (tid == 0) g_nflag = 0;
}
__global__ void fill_zero_kernel(float* p, int n) {
    int i = blockIdx.x * blockDim.x + threadIdx.x;
    if (i < n) p[i] = 0.0f;
}

// ---------------- tf32 mma.sync GEMM (cp.async, direct-B, register-cvt) --------
// C[M,N] = epi(A[M,K] @ W[K,N] + bias). W read directly (no pre-transpose).
// EPI: 0 relu-store, 1 plain store, 2 fused sum((v-X)^2) block partials.
// Block 256 thr = 8 warps (2x4); block tile 128 x BN; warp tile 64 x BN/4.
template <int BN, int EPI>
__global__ void __launch_bounds__(256, 2)
mma_gemm(const float* __restrict__ A, const float* __restrict__ W,
         const float* __restrict__ bias, float* __restrict__ C,
         const float* __restrict__ X, float* __restrict__ part,
         int N, int K) {
    extern __shared__ float smf[];
    constexpr int LDA = 36;                 // A smem stride (floats)
    constexpr int A_TILE_F = 128 * LDA;     // 4608
    constexpr int LDB = BN + 8;             // conflict-free for frag reads
    constexpr int B_TILE_F = 32 * LDB;
    constexpr int STAGE_F = A_TILE_F + B_TILE_F;
    constexpr int NTL = BN / 32;
    constexpr int WN = BN / 4;
    constexpr int BNC = BN / 4;             // 16B chunks per B row
    constexpr int B_CP = (32 * BNC) / 256;  // B chunks per thread

    const int tid = threadIdx.x;
    const int wid = tid >> 5;
    const int lane = tid & 31;
    const int g = lane >> 2;
    const int t = lane & 3;
    const int warp_m = wid >> 2;
    const int warp_n = wid & 3;
    const int bm = blockIdx.y * 128, bn = blockIdx.x * BN;
    const uint32_t sb = smem_u32(smf);

    float acc[4][NTL][4];
#pragma unroll
    for (int mt = 0; mt < 4; mt++)
#pragma unroll
        for (int nt = 0; nt < NTL; nt++)
#pragma unroll
            for (int i = 0; i < 4; i++) acc[mt][nt][i] = 0.0f;

    const int NC = K >> 5;

    auto prefetch = [&](int c, int s) {
        const int k0 = c << 5;
        const uint32_t base = sb + (uint32_t)s * STAGE_F * 4;
#pragma unroll
        for (int i = 0; i < 4; i++) {
            int idx = tid + i * 256;
            int r = idx >> 3, c4 = idx & 7;
            cp_async16(base + (r * LDA + c4 * 4) * 4,
                       &A[(size_t)(bm + r) * K + k0 + c4 * 4]);
        }
#pragma unroll
        for (int i = 0; i < B_CP; i++) {
            int idx = tid + i * 256;
            int r = idx / BNC, c4 = idx % BNC;
            cp_async16(base + (A_TILE_F + r * LDB + c4 * 4) * 4,
                       &W[(size_t)(k0 + r) * N + bn + c4 * 4]);
        }
    };

    auto compute = [&](int s) {
        const float* As = smf + s * STAGE_F;
        const float* Bs = As + A_TILE_F;
#pragma unroll
        for (int ks = 0; ks < 4; ks++) {
            const int kk = ks * 8 + t;
            uint32_t bh[NTL][2];
#pragma unroll
            for (int nt = 0; nt < NTL; nt++) {
                int nb = warp_n * WN + nt * 8 + g;
                bh[nt][0] = __float_as_uint(tf32_rna(Bs[kk * LDB + nb]));
                bh[nt][1] = __float_as_uint(tf32_rna(Bs[(kk + 4) * LDB + nb]));
            }
#pragma unroll
            for (int mt = 0; mt < 4; mt++) {
                int mb = warp_m * 64 + mt * 16 + g;
                uint32_t ah[4];
                ah[0] = __float_as_uint(tf32_rna(As[mb * LDA + kk]));
                ah[1] = __float_as_uint(tf32_rna(As[(mb + 8) * LDA + kk]));
                ah[2] = __float_as_uint(tf32_rna(As[mb * LDA + kk + 4]));
                ah[3] = __float_as_uint(tf32_rna(As[(mb + 8) * LDA + kk + 4]));
#pragma unroll
                for (int nt = 0; nt < NTL; nt++) MMA_TF32(acc[mt][nt], ah, bh[nt]);
            }
        }
    };

    // ---- pipelined mainloop (2-stage cp.async) ----
    prefetch(0, 0);
    CP_COMMIT();
    if (NC > 1) { prefetch(1, 1); CP_COMMIT(); CP_WAIT1(); }
    else        { CP_WAIT0(); }
    __syncthreads();
#pragma unroll 1
    for (int c = 0; c < NC; c++) {
        compute(c & 1);
        __syncthreads();
        if (c + 2 < NC) {
            prefetch(c + 2, c & 1);
            CP_COMMIT();
            CP_WAIT1();
        } else if (c + 1 < NC) {
            CP_WAIT0();
        }
        __syncthreads();
    }

    // ---- epilogue straight from accumulators ----
    float lsum = 0.0f;
#pragma unroll
    for (int mt = 0; mt < 4; mt++) {
#pragma unroll
        for (int nt = 0; nt < NTL; nt++) {
            int row = bm + warp_m * 64 + mt * 16 + g;
            int col = bn + warp_n * WN + nt * 8 + 2 * t;
            float b0 = bias[col], b1 = bias[col + 1];
            float v0 = acc[mt][nt][0] + b0, v1 = acc[mt][nt][1] + b1;
            float v2 = acc[mt][nt][2] + b0, v3 = acc[mt][nt][3] + b1;
            if (EPI == 0) {
                v0 = fmaxf(v0, 0.0f); v1 = fmaxf(v1, 0.0f);
                v2 = fmaxf(v2, 0.0f); v3 = fmaxf(v3, 0.0f);
            }
            size_t i0 = (size_t)row * N + col;
            size_t i1 = (size_t)(row + 8) * N + col;
            if (EPI == 2) {
                float2 x0 = *reinterpret_cast<const float2*>(&X[i0]);
                float2 x1 = *reinterpret_cast<const float2*>(&X[i1]);
                float d0 = v0 - x0.x, d1 = v1 - x0.y, d2 = v2 - x1.x, d3 = v3 - x1.y;
                lsum += d0 * d0 + d1 * d1 + d2 * d2 + d3 * d3;
            } else {
                *reinterpret_cast<float2*>(&C[i0]) = make_float2(v0, v1);
                *reinterpret_cast<float2*>(&C[i1]) = make_float2(v2, v3);
            }
        }
    }
    if (EPI == 2) {
        __syncthreads();
        smf[tid] = lsum;
        __syncthreads();
        for (int s2 = 128; s2 > 0; s2 >>= 1) {
            if (tid < s2) smf[tid] += smf[tid + s2];
            __syncthreads();
        }
        if (tid == 0) part[blockIdx.y * gridDim.x + blockIdx.x] = smf[0];
    }
}

// ---------------- clustering pass A -------------------------------------------
__global__ void cluster_pass(const float* __restrict__ t1,
                             const float* __restrict__ clu,
                             float* __restrict__ out_predict) {
    __shared__ float cs[KCLU * NZ];
    __shared__ float u_s[KCLU];
    __shared__ float red[256];
    int tid = threadIdx.x;
    for (int i = tid; i < KCLU * NZ; i += 256) cs[i] = clu[i];
    if (tid < KCLU) u_s[tid] = 0.0f;
    __syncthreads();

    int p = blockIdx.x * 256 + tid;
    float zr[NZ];
    const float* zp = g_z + (size_t)p * NZ;
#pragma unroll
    for (int i = 0; i < NZ; i++) zr[i] = zp[i];

    float cm = (t1[p * 3 + 0] * 0.01f) * (t1[p * 3 + 1] * 0.01f) * (t1[p * 3 + 2] * 0.01f)
               * 0.99f + 1.0f;
    float s = 0.0f;
#pragma unroll
    for (int i = 0; i < NZ; i++) { zr[i] *= cm; s += zr[i]; }
    float mean = s * (1.0f / NZ);
    float var = 0.0f;
#pragma unroll
    for (int i = 0; i < NZ; i++) { float d = zr[i] - mean; var += d * d; }
    float isd = 1.0f / sqrtf(var * (1.0f / (NZ - 1)));
#pragma unroll
    for (int i = 0; i < NZ; i++) zr[i] = (zr[i] - mean) * isd;

    float sumq = 0.0f, best = -1.0f, best2 = -1.0f;
    int bi = 0;
    for (int j = 0; j < KCLU; j++) {
        const float* c = &cs[j * NZ];
        float d = 0.0f;
#pragma unroll
        for (int i = 0; i < NZ; i++) { float tt = zr[i] - c[i]; d += tt * tt; }
        float qu = EPSF + d;
        sumq += qu;
        if (qu > best) { best2 = best; best = qu; bi = j; }
        else if (qu > best2) best2 = qu;
    }
    out_predict[p] = (float)bi;
    atomicAdd(&g_cnt[bi], 1);
    if (best - best2 < GAP_TAU * best) {       // near-tie: flag for fp32 rescue
        int ii = atomicAdd(&g_nflag, 1);
        g_flaglist[ii] = p;
    }

    float inv = 1.0f / sumq;
    float Sl = 0.0f;
    float* qrow = g_q + (size_t)p * KCLU;
    for (int j = 0; j < KCLU; j++) {
        const float* c = &cs[j * NZ];
        float d = 0.0f;
#pragma unroll
        for (int i = 0; i < NZ; i++) { float tt = zr[i] - c[i]; d += tt * tt; }
        float qn = (EPSF + d) * inv;
        qrow[j] = qn;
        atomicAdd(&u_s[j], qn);
        float lq = logf(qn);
        float tq = (1.0f - qn) * (1.0f - qn) * lq * INDEXF;
        Sl += sqrtf(-1.0f / tq);
    }

    red[tid] = Sl;
    __syncthreads();
    for (int s2 = 128; s2 > 0; s2 >>= 1) {
        if (tid < s2) red[tid] += red[tid + s2];
        __syncthreads();
    }
    if (tid == 0) g_Spart[blockIdx.x] = red[0];
    __syncthreads();
    if (tid < KCLU) g_upart[blockIdx.x * KCLU + tid] = u_s[tid];
}

// ---------------- fp32 rescue for near-tie points ------------------------------
// Transposed smem layout [k][point] -> per k: 2 broadcast LDS.128 + 8 FFMA.
#define RB 8
__global__ void __launch_bounds__(256, 1)
rescue_kernel(const float* __restrict__ x, const float* __restrict__ t1,
              const float* __restrict__ clu,
              const float* __restrict__ We1, const float* __restrict__ be1,
              const float* __restrict__ We2, const float* __restrict__ be2,
              const float* __restrict__ We3, const float* __restrict__ be3,
              const float* __restrict__ Wz,  const float* __restrict__ bz,
              float* __restrict__ out_predict) {
    extern __shared__ float sm[];
    float* xb  = sm;                  // [1024][RB]
    float* hh  = xb + RB * 1024;      // [2048][RB]
    float* s1b = hh + RB * 2048;      // [512][RB]
    float* s2b = s1b + RB * 512;      // [512][RB]
    float* zz  = s2b + RB * 512;      // [RB][32]
    float* pz  = zz + RB * 32;        // [8][32][RB] Lz partials
    float* dst = pz + 8 * 32 * RB;    // [128]
    const int tid = threadIdx.x;
    const int nf = g_nflag;

    for (int base = blockIdx.x * RB; base < nf; base += gridDim.x * RB) {
        const int cb = min(RB, nf - base);
        int plist[RB];
#pragma unroll
        for (int i = 0; i < RB; i++) plist[i] = g_flaglist[base + (i < cb ? i : 0)];
        __syncthreads();
        for (int k = tid; k < 1024; k += 256) {
#pragma unroll
            for (int i = 0; i < RB; i++)
                xb[k * RB + i] = x[(size_t)plist[i] * 1024 + k];
        }
        __syncthreads();
        // L1: 1024 -> 512 relu  (s1b[n][i])
        for (int n = tid; n < 512; n += 256) {
            float acc[RB] = {};
            for (int k = 0; k < 1024; k++) {
                float w = We1[(size_t)k * 512 + n];
                float4 v0 = *reinterpret_cast<const float4*>(&xb[k * RB]);
                float4 v1 = *reinterpret_cast<const float4*>(&xb[k * RB + 4]);
                acc[0] += v0.x * w; acc[1] += v0.y * w; acc[2] += v0.z * w; acc[3] += v0.w * w;
                acc[4] += v1.x * w; acc[5] += v1.y * w; acc[6] += v1.z * w; acc[7] += v1.w * w;
            }
            float b = be1[n];
#pragma unroll
            for (int i = 0; i < RB; i++) s1b[n * RB + i] = fmaxf(acc[i] + b, 0.0f);
        }
        __syncthreads();
        // L2: 512 -> 512 relu
        for (int n = tid; n < 512; n += 256) {
            float acc[RB] = {};
            for (int k = 0; k < 512; k++) {
                float w = We2[(size_t)k * 512 + n];
                float4 v0 = *reinterpret_cast<const float4*>(&s1b[k * RB]);
                float4 v1 = *reinterpret_cast<const float4*>(&s1b[k * RB + 4]);
                acc[0] += v0.x * w; acc[1] += v0.y * w; acc[2] += v0.z * w; acc[3] += v0.w * w;
                acc[4] += v1.x * w; acc[5] += v1.y * w; acc[6] += v1.z * w; acc[7] += v1.w * w;
            }
            float b = be2[n];
#pragma unroll
            for (int i = 0; i < RB; i++) s2b[n * RB + i] = fmaxf(acc[i] + b, 0.0f);
        }
        __syncthreads();
        // L3: 512 -> 2048 relu
        for (int n = tid; n < 2048; n += 256) {
            float acc[RB] = {};
            for (int k = 0; k < 512; k++) {
                float w = We3[(size_t)k * 2048 + n];
                float4 v0 = *reinterpret_cast<const float4*>(&s2b[k * RB]);
                float4 v1 = *reinterpret_cast<const float4*>(&s2b[k * RB + 4]);
                acc[0] += v0.x * w; acc[1] += v0.y * w; acc[2] += v0.z * w; acc[3] += v0.w * w;
                acc[4] += v1.x * w; acc[5] += v1.y * w; acc[6] += v1.z * w; acc[7] += v1.w * w;
            }
            float b = be3[n];
#pragma unroll
            for (int i = 0; i < RB; i++) hh[n * RB + i] = fmaxf(acc[i] + b, 0.0f);
        }
        __syncthreads();
        // Lz: 2048 -> 32 (no relu), chunked over k
        {
            int n = tid & 31, kc = tid >> 5;   // 8 chunks of 256
            float acc[RB] = {};
            for (int k = kc * 256; k < kc * 256 + 256; k++) {
                float w = Wz[(size_t)k * 32 + n];
                float4 v0 = *reinterpret_cast<const float4*>(&hh[k * RB]);
                float4 v1 = *reinterpret_cast<const float4*>(&hh[k * RB + 4]);
                acc[0] += v0.x * w; acc[1] += v0.y * w; acc[2] += v0.z * w; acc[3] += v0.w * w;
                acc[4] += v1.x * w; acc[5] += v1.y * w; acc[6] += v1.z * w; acc[7] += v1.w * w;
            }
#pragma unroll
            for (int i = 0; i < RB; i++) pz[(kc * 32 + n) * RB + i] = acc[i];
        }
        __syncthreads();
        if (tid < 32) {
            int n = tid;
            float b = bz[n];
#pragma unroll
            for (int i = 0; i < RB; i++) {
                float s = 0.0f;
                for (int kc = 0; kc < 8; kc++) s += pz[(kc * 32 + n) * RB + i];
                zz[i * 32 + n] = s + b;
            }
        }
        __syncthreads();
        // standardize (one thread per point)
        if (tid < cb) {
            int i = tid;
            int p = plist[i];
            float cm = (t1[p * 3 + 0] * 0.01f) * (t1[p * 3 + 1] * 0.01f) *
                       (t1[p * 3 + 2] * 0.01f) * 0.99f + 1.0f;
            float s = 0.0f;
            for (int k = 0; k < NZ; k++) { zz[i * 32 + k] *= cm; s += zz[i * 32 + k]; }
            float mean = s * (1.0f / NZ);
            float var = 0.0f;
            for (int k = 0; k < NZ; k++) { float d = zz[i * 32 + k] - mean; var += d * d; }
            float isd = 1.0f / sqrtf(var * (1.0f / (NZ - 1)));
            for (int k = 0; k < NZ; k++) zz[i * 32 + k] = (zz[i * 32 + k] - mean) * isd;
        }
        __syncthreads();
        // exact distances + argmax fix
        for (int i = 0; i < cb; i++) {
            if (tid < KCLU) {
                float d = 0.0f;
                for (int k = 0; k < NZ; k++) {
                    float tt = zz[i * 32 + k] - clu[tid * NZ + k];
                    d += tt * tt;
                }
                dst[tid] = d;
            }
            __syncthreads();
            if (tid == 0) {
                float best = -1.0f; int bi = 0;
                for (int j = 0; j < KCLU; j++)
                    if (dst[j] > best) { best = dst[j]; bi = j; }
                int p = plist[i];
                int old = (int)out_predict[p];
                if (old != bi) {
                    atomicAdd(&g_cnt[old], -1);
                    atomicAdd(&g_cnt[bi], 1);
                    out_predict[p] = (float)bi;
                }
            }
            __syncthreads();
        }
    }
}

// ---------------- stats pass B -------------------------------------------------
__global__ void stats_kernel() {
    __shared__ float u[KCLU];
    __shared__ float sred[128];
    int tid = threadIdx.x;
    if (tid < KCLU) {
        float s = 0.0f;
        for (int b = 0; b < NBLK_PTS; b++) s += g_upart[b * KCLU + tid];
        u[tid] = s;
    }
    float sp = (tid < NBLK_PTS) ? g_Spart[tid] : 0.0f;
    sred[tid] = sp;
    __syncthreads();
    for (int s = 64; s > 0; s >>= 1) {
        if (tid < s) sred[tid] += sred[tid + s];
        __syncthreads();
    }
    if (tid == 0) {
        float S = sred[0];
        float um = 0.0f;
        for (int j = 0; j < KCLU; j++) um += u[j];
        um /= KCLU;
        float uv = 0.0f;
        for (int j = 0; j < KCLU; j++) { float d = u[j] - um; uv += d * d; }
        float usd = sqrtf(uv / (KCLU - 1));

        float v[KCLU];
        float vm = 0.0f;
        for (int j = 0; j < KCLU; j++) {
            int c = g_cnt[j]; if (c < 1) c = 1;
            v[j] = sqrtf((float)c) * S;
            vm += v[j];
        }
        vm /= KCLU;
        float vv = 0.0f;
        for (int j = 0; j < KCLU; j++) { float d = v[j] - vm; vv += d * d; }
        float vsd = sqrtf(vv / (KCLU - 1));

        float umin = 1e30f, vmin = 1e30f;
        for (int j = 0; j < KCLU; j++) {
            float un = (u[j] - um) / usd;
            float vn = (v[j] - vm) / vsd;
            u[j] = un; v[j] = vn;
            if (un < umin) umin = un;
            if (vn < vmin) vmin = vn;
        }
        for (int j = 0; j < KCLU; j++)
            g_f[j] = (u[j] - umin + 0.001f) + (v[j] - vmin + 0.001f) + 1.0f;
    }
}

// ---------------- KL pass C -----------------------------------------------------
__global__ void kl_pass() {
    __shared__ float fs[KCLU];
    __shared__ float red[256];
    int tid = threadIdx.x;
    if (tid < KCLU) fs[tid] = g_f[tid];
    __syncthreads();
    int p = blockIdx.x * 256 + tid;
    const float* qrow = g_q + (size_t)p * KCLU;
    float sw = 0.0f;
    for (int j = 0; j < KCLU; j++) { float q = qrow[j]; sw += q * q / fs[j]; }
    float inv = 1.0f / sw;
    float kl = 0.0f;
    for (int j = 0; j < KCLU; j++) {
        float q = qrow[j];
        float pj = q * q / fs[j] * inv;
        kl += pj * (logf(pj) - logf(q));
    }
    red[tid] = kl;
    __syncthreads();
    for (int s2 = 128; s2 > 0; s2 >>= 1) {
        if (tid < s2) red[tid] += red[tid + s2];
        __syncthreads();
    }
    if (tid == 0) g_klpart[blockIdx.x] = red[0];
}

// ---------------- final loss ----------------------------------------------------
__global__ void final_kernel(const float* __restrict__ clu, float* __restrict__ out) {
    __shared__ float red[256];
    int tid = threadIdx.x;
    float kl = 0.0f;
    for (int i = tid; i < NBLK_PTS; i += 256) kl += g_klpart[i];
    float re = 0.0f;
    for (int i = tid; i < NBLK_RE; i += 256) re += g_repart[i];
    float D = 0.0f;
    for (int idx = tid; idx < KCLU * KCLU; idx += 256) {
        int i = idx / KCLU, j = idx % KCLU;
        float d = 0.0f;
        for (int kk = 0; kk < NZ; kk++) {
            float t = clu[i * NZ + kk] - clu[j * NZ + kk];
            d += t * t;
        }
        D += d;
    }
    red[tid] = kl; __syncthreads();
    for (int s = 128; s > 0; s >>= 1) { if (tid < s) red[tid] += red[tid + s]; __syncthreads(); }
    float kls = red[0]; __syncthreads();
    red[tid] = re; __syncthreads();
    for (int s = 128; s > 0; s >>= 1) { if (tid < s) red[tid] += red[tid + s]; __syncthreads(); }
    float res = red[0]; __syncthreads();
    red[tid] = D; __syncthreads();
    for (int s = 128; s > 0; s >>= 1) { if (tid < s) red[tid] += red[tid + s]; __syncthreads(); }
    if (tid == 0) {
        float kl_loss = 0.01f * kls / ((float)N_PTS * (float)KCLU);
        float re_loss = res / ((float)N_PTS * 1024.0f);
        float mean_d = red[0] / (float)(KCLU * KCLU - KCLU);
        out[N_PTS] = kl_loss + re_loss + 0.01f / mean_d;
    }
}

// ---------------- host ----------------------------------------------------------
extern "C" void kernel_launch(void* const* d_in, const int* in_sizes, int n_in,
                              void* d_out, int out_size) {
    const float* x   = (const float*)d_in[0];
    const float* t1  = (const float*)d_in[1];
    const float* clu = (const float*)d_in[2];
    const float* We1 = (const float*)d_in[3];  const float* be1 = (const float*)d_in[4];
    const float* We2 = (const float*)d_in[5];  const float* be2 = (const float*)d_in[6];
    const float* We3 = (const float*)d_in[7];  const float* be3 = (const float*)d_in[8];
    const float* Wz  = (const float*)d_in[9];  const float* bz  = (const float*)d_in[10];
    const float* Wd1 = (const float*)d_in[11]; const float* bd1 = (const float*)d_in[12];
    const float* Wd2 = (const float*)d_in[13]; const float* bd2 = (const float*)d_in[14];
    const float* Wd3 = (const float*)d_in[15]; const float* bd3 = (const float*)d_in[16];
    const float* Wxb = (const float*)d_in[17]; const float* bxb = (const float*)d_in[18];
    float* out = (float*)d_out;

    float *P, *h1, *h2, *zb, *repart;
    cudaGetSymbolAddress((void**)&P,  g_P);
    cudaGetSymbolAddress((void**)&h1, g_h1);
    cudaGetSymbolAddress((void**)&h2, g_h2);
    cudaGetSymbolAddress((void**)&zb, g_z);
    cudaGetSymbolAddress((void**)&repart, g_repart);

    constexpr int SM_128 = (128 * 36 + 32 * 136) * 2 * 4;   // 71680 B
    constexpr int SM_32  = (128 * 36 + 32 * 40) * 2 * 4;    // 47104 B
    constexpr int SM_RES = (RB * 1024 + RB * 2048 + RB * 512 + RB * 512 + RB * 32
                            + 8 * 32 * RB + 128) * 4;        // 140800 B
    cudaFuncSetAttribute(mma_gemm<128, 0>, cudaFuncAttributeMaxDynamicSharedMemorySize, SM_128);
    cudaFuncSetAttribute(mma_gemm<32, 1>,  cudaFuncAttributeMaxDynamicSharedMemorySize, SM_32);
    cudaFuncSetAttribute(mma_gemm<128, 2>, cudaFuncAttributeMaxDynamicSharedMemorySize, SM_128);
    cudaFuncSetAttribute(rescue_kernel, cudaFuncAttributeMaxDynamicSharedMemorySize, SM_RES);

    init_kernel<<<1, 128>>>();

    const dim3 blk(256);
    const int MB = N_PTS / 128;  // 232

    // encoder (single-pass tf32; rescue fixes near-tie argmaxes)
    mma_gemm<128, 0><<<dim3(4, MB), blk, SM_128>>>(x, We1, be1, h1, nullptr, nullptr, 512, 1024);
    mma_gemm<128, 0><<<dim3(4, MB), blk, SM_128>>>(h1, We2, be2, h2, nullptr, nullptr, 512, 512);
    mma_gemm<128, 0><<<dim3(16, MB), blk, SM_128>>>(h2, We3, be3, P, nullptr, nullptr, 2048, 512);
    mma_gemm<32, 1><<<dim3(1, MB), blk, SM_32>>>(P, Wz, bz, zb, nullptr, nullptr, 32, 2048);
    // decoder (single-pass tf32)
    mma_gemm<128, 0><<<dim3(16, MB), blk, SM_128>>>(zb, Wd1, bd1, P, nullptr, nullptr, 2048, 32);
    mma_gemm<128, 0><<<dim3(4, MB), blk, SM_128>>>(P, Wd2, bd2, h1, nullptr, nullptr, 512, 2048);
    mma_gemm<128, 0><<<dim3(4, MB), blk, SM_128>>>(h1, Wd3, bd3, h2, nullptr, nullptr, 512, 512);
    mma_gemm<128, 2><<<dim3(8, MB), blk, SM_128>>>(h2, Wxb, bxb, nullptr, x, repart, 1024, 512);

    // clustering + rescue + loss
    cluster_pass<<<NBLK_PTS, 256>>>(t1, clu, out);
    rescue_kernel<<<148, 256, SM_RES>>>(x, t1, clu, We1, be1, We2, be2, We3, be3, Wz, bz, out);
    stats_kernel<<<1, 128>>>();
    kl_pass<<<NBLK_PTS, 256>>>();
    final_kernel<<<1, 256>>>(clu, out);

    int extra = out_size - (N_PTS + 1);
    if (extra > 0) fill_zero_kernel<<<(extra + 255) / 256, 256>>>(out + N_PTS + 1, extra);
}

// round 10
// speedup vs baseline: 2.2795x; 1.0598x over previous
#include <cuda_runtime.h>
#include <math.h>
#include <stdint.h>

#define N_PTS   29696
#define NZ      32
#define KCLU    100
#define EPSF    1e-5f
#define INDEXF  29696.0f
#define NBLK_PTS 116          // N_PTS / 256
#define NBLK_RE  1856         // (1024/128) * (29696/128)
#define GAP_TAU 5e-3f

// ---------------- scratch (static device globals; no allocation) -------------
__device__ float g_P [(size_t)N_PTS * 2048];   // h3, then d1
__device__ float g_h1[(size_t)N_PTS * 512];    // h1, then d2
__device__ float g_h2[(size_t)N_PTS * 512];    // h2, then d3
__device__ float g_z [(size_t)N_PTS * NZ];
__device__ float g_q [(size_t)N_PTS * KCLU];
__device__ float g_wr[3712 * 1024];            // pre-rounded weights (offsets below)
__device__ float g_upart[NBLK_PTS * KCLU];
__device__ float g_Spart[NBLK_PTS];
__device__ float g_klpart[NBLK_PTS];
__device__ float g_repart[NBLK_RE];
__device__ int   g_cnt[KCLU];
__device__ float g_f[KCLU];
__device__ int   g_nflag;
__device__ int   g_flaglist[N_PTS];

// offsets (floats) into g_wr
#define OFF_WE1 0            // 1024*512
#define OFF_WE2 (512*1024)   // 512*512
#define OFF_WE3 (768*1024)   // 512*2048
#define OFF_WZ  (1792*1024)  // 2048*32
#define OFF_WD1 (1856*1024)  // 32*2048
#define OFF_WD2 (1920*1024)  // 2048*512
#define OFF_WD3 (2944*1024)  // 512*512
#define OFF_WXB (3200*1024)  // 512*1024

// ---------------- helpers ------------------------------------------------------
__device__ __forceinline__ float tf32_rna(float x) {
    uint32_t u;
    asm("cvt.rna.tf32.f32 %0, %1;" : "=r"(u) : "f"(x));
    return __uint_as_float(u);
}
__device__ __forceinline__ uint32_t smem_u32(const void* p) {
    uint32_t a;
    asm("{ .reg .u64 t; cvta.to.shared.u64 t, %1; cvt.u32.u64 %0, t; }" : "=r"(a) : "l"(p));
    return a;
}
__device__ __forceinline__ void cp_async16(uint32_t s, const void* g) {
    asm volatile("cp.async.cg.shared.global [%0], [%1], 16;" :: "r"(s), "l"(g));
}
#define CP_COMMIT() asm volatile("cp.async.commit_group;" ::: "memory")
#define CP_WAIT1()  asm volatile("cp.async.wait_group 1;" ::: "memory")
#define CP_WAIT0()  asm volatile("cp.async.wait_group 0;" ::: "memory")
#define MMA_TF32(c, a, b) \
    asm volatile("mma.sync.aligned.m16n8k8.row.col.f32.tf32.tf32.f32 " \
        "{%0,%1,%2,%3}, {%4,%5,%6,%7}, {%8,%9}, {%0,%1,%2,%3};" \
        : "+f"((c)[0]), "+f"((c)[1]), "+f"((c)[2]), "+f"((c)[3]) \
        : "r"((a)[0]), "r"((a)[1]), "r"((a)[2]), "r"((a)[3]), \
          "r"((b)[0]), "r"((b)[1]))

__global__ void init_kernel() {
    int tid = threadIdx.x;
    if (tid < KCLU) g_cnt[tid] = 0;
    if (tid == 0) g_nflag = 0;
}
__global__ void fill_zero_kernel(float* p, int n) {
    int i = blockIdx.x * blockDim.x + threadIdx.x;
    if (i < n) p[i] = 0.0f;
}
// round weights to tf32 once (n4 = count/4)
__global__ void round4_kernel(const float4* __restrict__ in, float4* __restrict__ out, int n4) {
    int i = blockIdx.x * blockDim.x + threadIdx.x;
    if (i < n4) {
        float4 v = in[i];
        v.x = tf32_rna(v.x); v.y = tf32_rna(v.y);
        v.z = tf32_rna(v.z); v.w = tf32_rna(v.w);
        out[i] = v;
    }
}

// ---------------- tf32 mma.sync GEMM (cp.async, swizzled A, pre-rounded) -------
// C[M,N] = epi(A[M,K] @ W[K,N] + bias). W pre-rounded to tf32.
// CVT_A: 1 -> A raw fp32, cvt in registers; 0 -> A already tf32-rounded.
// EPI: 0 relu+round store, 1 plain raw store, 2 fused sum((v-X)^2) partials.
template <int BN, int CVT_A, int EPI>
__global__ void __launch_bounds__(256, 2)
mma_gemm(const float* __restrict__ A, const float* __restrict__ W,
         const float* __restrict__ bias, float* __restrict__ C,
         const float* __restrict__ X, float* __restrict__ part,
         int N, int K) {
    extern __shared__ float smf[];
    constexpr int A_TILE_F = 128 * 32;      // swizzled, stride 32 (no pad)
    constexpr int LDB = BN + 8;
    constexpr int B_TILE_F = 32 * LDB;
    constexpr int STAGE_F = A_TILE_F + B_TILE_F;
    constexpr int NTL = BN / 32;
    constexpr int WN = BN / 4;
    constexpr int BNC = BN / 4;
    constexpr int B_CP = (32 * BNC) / 256;

    const int tid = threadIdx.x;
    const int wid = tid >> 5;
    const int lane = tid & 31;
    const int g = lane >> 2;
    const int t = lane & 3;
    const int warp_m = wid >> 2;
    const int warp_n = wid & 3;
    const int bm = blockIdx.y * 128, bn = blockIdx.x * BN;
    const uint32_t sb = smem_u32(smf);

    float acc[4][NTL][4];
#pragma unroll
    for (int mt = 0; mt < 4; mt++)
#pragma unroll
        for (int nt = 0; nt < NTL; nt++)
#pragma unroll
            for (int i = 0; i < 4; i++) acc[mt][nt][i] = 0.0f;

    const int NC = K >> 5;

    auto prefetch = [&](int c, int s) {
        const int k0 = c << 5;
        const uint32_t base = sb + (uint32_t)s * STAGE_F * 4;
#pragma unroll
        for (int i = 0; i < 4; i++) {
            int idx = tid + i * 256;
            int r = idx >> 3, c4 = idx & 7;
            int c4s = c4 ^ (r & 7);                       // XOR swizzle
            cp_async16(base + (r * 32 + c4s * 4) * 4,
                       &A[(size_t)(bm + r) * K + k0 + c4 * 4]);
        }
#pragma unroll
        for (int i = 0; i < B_CP; i++) {
            int idx = tid + i * 256;
            int r = idx / BNC, c4 = idx % BNC;
            cp_async16(base + (A_TILE_F + r * LDB + c4 * 4) * 4,
                       &W[(size_t)(k0 + r) * N + bn + c4 * 4]);
        }
    };

    auto compute = [&](int s) {
        const float* As = smf + s * STAGE_F;
        const float* Bs = As + A_TILE_F;
#pragma unroll
        for (int ks = 0; ks < 4; ks++) {
            const int kk = ks * 8 + t;
            const int c0 = 2 * ks, c1 = 2 * ks + 1;       // float4 chunks of kk, kk+4
            uint32_t bh[NTL][2];
#pragma unroll
            for (int nt = 0; nt < NTL; nt++) {
                int nb = warp_n * WN + nt * 8 + g;
                bh[nt][0] = __float_as_uint(Bs[kk * LDB + nb]);
                bh[nt][1] = __float_as_uint(Bs[(kk + 4) * LDB + nb]);
            }
#pragma unroll
            for (int mt = 0; mt < 4; mt++) {
                int r0 = warp_m * 64 + mt * 16 + g;       // r0&7 == g
                float a0 = As[r0 * 32 + ((c0 ^ g) << 2) + t];
                float a1 = As[(r0 + 8) * 32 + ((c0 ^ g) << 2) + t];
                float a2 = As[r0 * 32 + ((c1 ^ g) << 2) + t];
                float a3 = As[(r0 + 8) * 32 + ((c1 ^ g) << 2) + t];
                if (CVT_A) {
                    a0 = tf32_rna(a0); a1 = tf32_rna(a1);
                    a2 = tf32_rna(a2); a3 = tf32_rna(a3);
                }
                uint32_t ah[4] = { __float_as_uint(a0), __float_as_uint(a1),
                                   __float_as_uint(a2), __float_as_uint(a3) };
#pragma unroll
                for (int nt = 0; nt < NTL; nt++) MMA_TF32(acc[mt][nt], ah, bh[nt]);
            }
        }
    };

    // ---- pipelined mainloop (2-stage cp.async) ----
    prefetch(0, 0);
    CP_COMMIT();
    if (NC > 1) { prefetch(1, 1); CP_COMMIT(); CP_WAIT1(); }
    else        { CP_WAIT0(); }
    __syncthreads();
#pragma unroll 1
    for (int c = 0; c < NC; c++) {
        compute(c & 1);
        __syncthreads();
        if (c + 2 < NC) {
            prefetch(c + 2, c & 1);
            CP_COMMIT();
            CP_WAIT1();
        } else if (c + 1 < NC) {
            CP_WAIT0();
        }
        __syncthreads();
    }

    // ---- epilogue straight from accumulators ----
    float lsum = 0.0f;
#pragma unroll
    for (int mt = 0; mt < 4; mt++) {
#pragma unroll
        for (int nt = 0; nt < NTL; nt++) {
            int row = bm + warp_m * 64 + mt * 16 + g;
            int col = bn + warp_n * WN + nt * 8 + 2 * t;
            float b0 = bias[col], b1 = bias[col + 1];
            float v0 = acc[mt][nt][0] + b0, v1 = acc[mt][nt][1] + b1;
            float v2 = acc[mt][nt][2] + b0, v3 = acc[mt][nt][3] + b1;
            if (EPI == 0) {                               // relu + pre-round for next GEMM
                v0 = tf32_rna(fmaxf(v0, 0.0f)); v1 = tf32_rna(fmaxf(v1, 0.0f));
                v2 = tf32_rna(fmaxf(v2, 0.0f)); v3 = tf32_rna(fmaxf(v3, 0.0f));
            }
            size_t i0 = (size_t)row * N + col;
            size_t i1 = (size_t)(row + 8) * N + col;
            if (EPI == 2) {
                float2 x0 = *reinterpret_cast<const float2*>(&X[i0]);
                float2 x1 = *reinterpret_cast<const float2*>(&X[i1]);
                float d0 = v0 - x0.x, d1 = v1 - x0.y, d2 = v2 - x1.x, d3 = v3 - x1.y;
                lsum += d0 * d0 + d1 * d1 + d2 * d2 + d3 * d3;
            } else {
                *reinterpret_cast<float2*>(&C[i0]) = make_float2(v0, v1);
                *reinterpret_cast<float2*>(&C[i1]) = make_float2(v2, v3);
            }
        }
    }
    if (EPI == 2) {
        __syncthreads();
        smf[tid] = lsum;
        __syncthreads();
        for (int s2 = 128; s2 > 0; s2 >>= 1) {
            if (tid < s2) smf[tid] += smf[tid + s2];
            __syncthreads();
        }
        if (tid == 0) part[blockIdx.y * gridDim.x + blockIdx.x] = smf[0];
    }
}

// ---------------- clustering pass A -------------------------------------------
__global__ void cluster_pass(const float* __restrict__ t1,
                             const float* __restrict__ clu,
                             float* __restrict__ out_predict) {
    __shared__ float cs[KCLU * NZ];
    __shared__ float u_s[KCLU];
    __shared__ float red[256];
    int tid = threadIdx.x;
    for (int i = tid; i < KCLU * NZ; i += 256) cs[i] = clu[i];
    if (tid < KCLU) u_s[tid] = 0.0f;
    __syncthreads();

    int p = blockIdx.x * 256 + tid;
    float zr[NZ];
    const float* zp = g_z + (size_t)p * NZ;
#pragma unroll
    for (int i = 0; i < NZ; i++) zr[i] = zp[i];

    float cm = (t1[p * 3 + 0] * 0.01f) * (t1[p * 3 + 1] * 0.01f) * (t1[p * 3 + 2] * 0.01f)
               * 0.99f + 1.0f;
    float s = 0.0f;
#pragma unroll
    for (int i = 0; i < NZ; i++) { zr[i] *= cm; s += zr[i]; }
    float mean = s * (1.0f / NZ);
    float var = 0.0f;
#pragma unroll
    for (int i = 0; i < NZ; i++) { float d = zr[i] - mean; var += d * d; }
    float isd = 1.0f / sqrtf(var * (1.0f / (NZ - 1)));
#pragma unroll
    for (int i = 0; i < NZ; i++) zr[i] = (zr[i] - mean) * isd;

    float sumq = 0.0f, best = -1.0f, best2 = -1.0f;
    int bi = 0;
    for (int j = 0; j < KCLU; j++) {
        const float* c = &cs[j * NZ];
        float d = 0.0f;
#pragma unroll
        for (int i = 0; i < NZ; i++) { float tt = zr[i] - c[i]; d += tt * tt; }
        float qu = EPSF + d;
        sumq += qu;
        if (qu > best) { best2 = best; best = qu; bi = j; }
        else if (qu > best2) best2 = qu;
    }
    out_predict[p] = (float)bi;
    atomicAdd(&g_cnt[bi], 1);
    if (best - best2 < GAP_TAU * best) {
        int ii = atomicAdd(&g_nflag, 1);
        g_flaglist[ii] = p;
    }

    float inv = 1.0f / sumq;
    float Sl = 0.0f;
    float* qrow = g_q + (size_t)p * KCLU;
    for (int j = 0; j < KCLU; j++) {
        const float* c = &cs[j * NZ];
        float d = 0.0f;
#pragma unroll
        for (int i = 0; i < NZ; i++) { float tt = zr[i] - c[i]; d += tt * tt; }
        float qn = (EPSF + d) * inv;
        qrow[j] = qn;
        atomicAdd(&u_s[j], qn);
        float lq = logf(qn);
        float tq = (1.0f - qn) * (1.0f - qn) * lq * INDEXF;
        Sl += sqrtf(-1.0f / tq);
    }

    red[tid] = Sl;
    __syncthreads();
    for (int s2 = 128; s2 > 0; s2 >>= 1) {
        if (tid < s2) red[tid] += red[tid + s2];
        __syncthreads();
    }
    if (tid == 0) g_Spart[blockIdx.x] = red[0];
    __syncthreads();
    if (tid < KCLU) g_upart[blockIdx.x * KCLU + tid] = u_s[tid];
}

// ---------------- fp32 rescue for near-tie points ------------------------------
#define RB 8
__global__ void __launch_bounds__(256, 1)
rescue_kernel(const float* __restrict__ x, const float* __restrict__ t1,
              const float* __restrict__ clu,
              const float* __restrict__ We1, const float* __restrict__ be1,
              const float* __restrict__ We2, const float* __restrict__ be2,
              const float* __restrict__ We3, const float* __restrict__ be3,
              const float* __restrict__ Wz,  const float* __restrict__ bz,
              float* __restrict__ out_predict) {
    extern __shared__ float sm[];
    float* xb  = sm;                  // [1024][RB]
    float* hh  = xb + RB * 1024;      // [2048][RB]
    float* s1b = hh + RB * 2048;      // [512][RB]
    float* s2b = s1b + RB * 512;      // [512][RB]
    float* zz  = s2b + RB * 512;      // [RB][32]
    float* pz  = zz + RB * 32;        // [8][32][RB]
    float* dst = pz + 8 * 32 * RB;    // [128]
    const int tid = threadIdx.x;
    const int nf = g_nflag;

    for (int base = blockIdx.x * RB; base < nf; base += gridDim.x * RB) {
        const int cb = min(RB, nf - base);
        int plist[RB];
#pragma unroll
        for (int i = 0; i < RB; i++) plist[i] = g_flaglist[base + (i < cb ? i : 0)];
        __syncthreads();
        for (int k = tid; k < 1024; k += 256) {
#pragma unroll
            for (int i = 0; i < RB; i++)
                xb[k * RB + i] = x[(size_t)plist[i] * 1024 + k];
        }
        __syncthreads();
        for (int n = tid; n < 512; n += 256) {
            float acc[RB] = {};
            for (int k = 0; k < 1024; k++) {
                float w = We1[(size_t)k * 512 + n];
                float4 v0 = *reinterpret_cast<const float4*>(&xb[k * RB]);
                float4 v1 = *reinterpret_cast<const float4*>(&xb[k * RB + 4]);
                acc[0] += v0.x * w; acc[1] += v0.y * w; acc[2] += v0.z * w; acc[3] += v0.w * w;
                acc[4] += v1.x * w; acc[5] += v1.y * w; acc[6] += v1.z * w; acc[7] += v1.w * w;
            }
            float b = be1[n];
#pragma unroll
            for (int i = 0; i < RB; i++) s1b[n * RB + i] = fmaxf(acc[i] + b, 0.0f);
        }
        __syncthreads();
        for (int n = tid; n < 512; n += 256) {
            float acc[RB] = {};
            for (int k = 0; k < 512; k++) {
                float w = We2[(size_t)k * 512 + n];
                float4 v0 = *reinterpret_cast<const float4*>(&s1b[k * RB]);
                float4 v1 = *reinterpret_cast<const float4*>(&s1b[k * RB + 4]);
                acc[0] += v0.x * w; acc[1] += v0.y * w; acc[2] += v0.z * w; acc[3] += v0.w * w;
                acc[4] += v1.x * w; acc[5] += v1.y * w; acc[6] += v1.z * w; acc[7] += v1.w * w;
            }
            float b = be2[n];
#pragma unroll
            for (int i = 0; i < RB; i++) s2b[n * RB + i] = fmaxf(acc[i] + b, 0.0f);
        }
        __syncthreads();
        for (int n = tid; n < 2048; n += 256) {
            float acc[RB] = {};
            for (int k = 0; k < 512; k++) {
                float w = We3[(size_t)k * 2048 + n];
                float4 v0 = *reinterpret_cast<const float4*>(&s2b[k * RB]);
                float4 v1 = *reinterpret_cast<const float4*>(&s2b[k * RB + 4]);
                acc[0] += v0.x * w; acc[1] += v0.y * w; acc[2] += v0.z * w; acc[3] += v0.w * w;
                acc[4] += v1.x * w; acc[5] += v1.y * w; acc[6] += v1.z * w; acc[7] += v1.w * w;
            }
            float b = be3[n];
#pragma unroll
            for (int i = 0; i < RB; i++) hh[n * RB + i] = fmaxf(acc[i] + b, 0.0f);
        }
        __syncthreads();
        {
            int n = tid & 31, kc = tid >> 5;
            float acc[RB] = {};
            for (int k = kc * 256; k < kc * 256 + 256; k++) {
                float w = Wz[(size_t)k * 32 + n];
                float4 v0 = *reinterpret_cast<const float4*>(&hh[k * RB]);
                float4 v1 = *reinterpret_cast<const float4*>(&hh[k * RB + 4]);
                acc[0] += v0.x * w; acc[1] += v0.y * w; acc[2] += v0.z * w; acc[3] += v0.w * w;
                acc[4] += v1.x * w; acc[5] += v1.y * w; acc[6] += v1.z * w; acc[7] += v1.w * w;
            }
#pragma unroll
            for (int i = 0; i < RB; i++) pz[(kc * 32 + n) * RB + i] = acc[i];
        }
        __syncthreads();
        if (tid < 32) {
            int n = tid;
            float b = bz[n];
#pragma unroll
            for (int i = 0; i < RB; i++) {
                float s = 0.0f;
                for (int kc = 0; kc < 8; kc++) s += pz[(kc * 32 + n) * RB + i];
                zz[i * 32 + n] = s + b;
            }
        }
        __syncthreads();
        if (tid < cb) {
            int i = tid;
            int p = plist[i];
            float cm = (t1[p * 3 + 0] * 0.01f) * (t1[p * 3 + 1] * 0.01f) *
                       (t1[p * 3 + 2] * 0.01f) * 0.99f + 1.0f;
            float s = 0.0f;
            for (int k = 0; k < NZ; k++) { zz[i * 32 + k] *= cm; s += zz[i * 32 + k]; }
            float mean = s * (1.0f / NZ);
            float var = 0.0f;
            for (int k = 0; k < NZ; k++) { float d = zz[i * 32 + k] - mean; var += d * d; }
            float isd = 1.0f / sqrtf(var * (1.0f / (NZ - 1)));
            for (int k = 0; k < NZ; k++) zz[i * 32 + k] = (zz[i * 32 + k] - mean) * isd;
        }
        __syncthreads();
        for (int i = 0; i < cb; i++) {
            if (tid < KCLU) {
                float d = 0.0f;
                for (int k = 0; k < NZ; k++) {
                    float tt = zz[i * 32 + k] - clu[tid * NZ + k];
                    d += tt * tt;
                }
                dst[tid] = d;
            }
            __syncthreads();
            if (tid == 0) {
                float best = -1.0f; int bi = 0;
                for (int j = 0; j < KCLU; j++)
                    if (dst[j] > best) { best = dst[j]; bi = j; }
                int p = plist[i];
                int old = (int)out_predict[p];
                if (old != bi) {
                    atomicAdd(&g_cnt[old], -1);
                    atomicAdd(&g_cnt[bi], 1);
                    out_predict[p] = (float)bi;
                }
            }
            __syncthreads();
        }
    }
}

// ---------------- stats pass B -------------------------------------------------
__global__ void stats_kernel() {
    __shared__ float u[KCLU];
    __shared__ float sred[128];
    int tid = threadIdx.x;
    if (tid < KCLU) {
        float s = 0.0f;
        for (int b = 0; b < NBLK_PTS; b++) s += g_upart[b * KCLU + tid];
        u[tid] = s;
    }
    float sp = (tid < NBLK_PTS) ? g_Spart[tid] : 0.0f;
    sred[tid] = sp;
    __syncthreads();
    for (int s = 64; s > 0; s >>= 1) {
        if (tid < s) sred[tid] += sred[tid + s];
        __syncthreads();
    }
    if (tid == 0) {
        float S = sred[0];
        float um = 0.0f;
        for (int j = 0; j < KCLU; j++) um += u[j];
        um /= KCLU;
        float uv = 0.0f;
        for (int j = 0; j < KCLU; j++) { float d = u[j] - um; uv += d * d; }
        float usd = sqrtf(uv / (KCLU - 1));

        float v[KCLU];
        float vm = 0.0f;
        for (int j = 0; j < KCLU; j++) {
            int c = g_cnt[j]; if (c < 1) c = 1;
            v[j] = sqrtf((float)c) * S;
            vm += v[j];
        }
        vm /= KCLU;
        float vv = 0.0f;
        for (int j = 0; j < KCLU; j++) { float d = v[j] - vm; vv += d * d; }
        float vsd = sqrtf(vv / (KCLU - 1));

        float umin = 1e30f, vmin = 1e30f;
        for (int j = 0; j < KCLU; j++) {
            float un = (u[j] - um) / usd;
            float vn = (v[j] - vm) / vsd;
            u[j] = un; v[j] = vn;
            if (un < umin) umin = un;
            if (vn < vmin) vmin = vn;
        }
        for (int j = 0; j < KCLU; j++)
            g_f[j] = (u[j] - umin + 0.001f) + (v[j] - vmin + 0.001f) + 1.0f;
    }
}

// ---------------- KL pass C -----------------------------------------------------
__global__ void kl_pass() {
    __shared__ float fs[KCLU];
    __shared__ float red[256];
    int tid = threadIdx.x;
    if (tid < KCLU) fs[tid] = g_f[tid];
    __syncthreads();
    int p = blockIdx.x * 256 + tid;
    const float* qrow = g_q + (size_t)p * KCLU;
    float sw = 0.0f;
    for (int j = 0; j < KCLU; j++) { float q = qrow[j]; sw += q * q / fs[j]; }
    float inv = 1.0f / sw;
    float kl = 0.0f;
    for (int j = 0; j < KCLU; j++) {
        float q = qrow[j];
        float pj = q * q / fs[j] * inv;
        kl += pj * (logf(pj) - logf(q));
    }
    red[tid] = kl;
    __syncthreads();
    for (int s2 = 128; s2 > 0; s2 >>= 1) {
        if (tid < s2) red[tid] += red[tid + s2];
        __syncthreads();
    }
    if (tid == 0) g_klpart[blockIdx.x] = red[0];
}

// ---------------- final loss ----------------------------------------------------
__global__ void final_kernel(const float* __restrict__ clu, float* __restrict__ out) {
    __shared__ float red[256];
    int tid = threadIdx.x;
    float kl = 0.0f;
    for (int i = tid; i < NBLK_PTS; i += 256) kl += g_klpart[i];
    float re = 0.0f;
    for (int i = tid; i < NBLK_RE; i += 256) re += g_repart[i];
    float D = 0.0f;
    for (int idx = tid; idx < KCLU * KCLU; idx += 256) {
        int i = idx / KCLU, j = idx % KCLU;
        float d = 0.0f;
        for (int kk = 0; kk < NZ; kk++) {
            float t = clu[i * NZ + kk] - clu[j * NZ + kk];
            d += t * t;
        }
        D += d;
    }
    red[tid] = kl; __syncthreads();
    for (int s = 128; s > 0; s >>= 1) { if (tid < s) red[tid] += red[tid + s]; __syncthreads(); }
    float kls = red[0]; __syncthreads();
    red[tid] = re; __syncthreads();
    for (int s = 128; s > 0; s >>= 1) { if (tid < s) red[tid] += red[tid + s]; __syncthreads(); }
    float res = red[0]; __syncthreads();
    red[tid] = D; __syncthreads();
    for (int s = 128; s > 0; s >>= 1) { if (tid < s) red[tid] += red[tid + s]; __syncthreads(); }
    if (tid == 0) {
        float kl_loss = 0.01f * kls / ((float)N_PTS * (float)KCLU);
        float re_loss = res / ((float)N_PTS * 1024.0f);
        float mean_d = red[0] / (float)(KCLU * KCLU - KCLU);
        out[N_PTS] = kl_loss + re_loss + 0.01f / mean_d;
    }
}

// ---------------- host ----------------------------------------------------------
extern "C" void kernel_launch(void* const* d_in, const int* in_sizes, int n_in,
                              void* d_out, int out_size) {
    const float* x   = (const float*)d_in[0];
    const float* t1  = (const float*)d_in[1];
    const float* clu = (const float*)d_in[2];
    const float* We1 = (const float*)d_in[3];  const float* be1 = (const float*)d_in[4];
    const float* We2 = (const float*)d_in[5];  const float* be2 = (const float*)d_in[6];
    const float* We3 = (const float*)d_in[7];  const float* be3 = (const float*)d_in[8];
    const float* Wz  = (const float*)d_in[9];  const float* bz  = (const float*)d_in[10];
    const float* Wd1 = (const float*)d_in[11]; const float* bd1 = (const float*)d_in[12];
    const float* Wd2 = (const float*)d_in[13]; const float* bd2 = (const float*)d_in[14];
    const float* Wd3 = (const float*)d_in[15]; const float* bd3 = (const float*)d_in[16];
    const float* Wxb = (const float*)d_in[17]; const float* bxb = (const float*)d_in[18];
    float* out = (float*)d_out;

    float *P, *h1, *h2, *zb, *wr, *repart;
    cudaGetSymbolAddress((void**)&P,  g_P);
    cudaGetSymbolAddress((void**)&h1, g_h1);
    cudaGetSymbolAddress((void**)&h2, g_h2);
    cudaGetSymbolAddress((void**)&zb, g_z);
    cudaGetSymbolAddress((void**)&wr, g_wr);
    cudaGetSymbolAddress((void**)&repart, g_repart);

    constexpr int SM_128 = (128 * 32 + 32 * 136) * 2 * 4;   // 67584 B
    constexpr int SM_32  = (128 * 32 + 32 * 40) * 2 * 4;    // 43008 B
    constexpr int SM_RES = (RB * 1024 + RB * 2048 + RB * 512 + RB * 512 + RB * 32
                            + 8 * 32 * RB + 128) * 4;
    cudaFuncSetAttribute(mma_gemm<128, 0, 0>, cudaFuncAttributeMaxDynamicSharedMemorySize, SM_128);
    cudaFuncSetAttribute(mma_gemm<128, 1, 0>, cudaFuncAttributeMaxDynamicSharedMemorySize, SM_128);
    cudaFuncSetAttribute(mma_gemm<32, 0, 1>,  cudaFuncAttributeMaxDynamicSharedMemorySize, SM_32);
    cudaFuncSetAttribute(mma_gemm<128, 0, 2>, cudaFuncAttributeMaxDynamicSharedMemorySize, SM_128);
    cudaFuncSetAttribute(rescue_kernel, cudaFuncAttributeMaxDynamicSharedMemorySize, SM_RES);

    init_kernel<<<1, 128>>>();

    // pre-round all weights to tf32 (one pass each; independent)
    auto R4 = [&](const float* w, int off, int n) {
        round4_kernel<<<(n / 4 + 255) / 256, 256>>>(
            (const float4*)w, (float4*)(wr + off), n / 4);
    };
    R4(We1, OFF_WE1, 1024 * 512);
    R4(We2, OFF_WE2, 512 * 512);
    R4(We3, OFF_WE3, 512 * 2048);
    R4(Wz,  OFF_WZ,  2048 * 32);
    R4(Wd1, OFF_WD1, 32 * 2048);
    R4(Wd2, OFF_WD2, 2048 * 512);
    R4(Wd3, OFF_WD3, 512 * 512);
    R4(Wxb, OFF_WXB, 512 * 1024);

    const dim3 blk(256);
    const int MB = N_PTS / 128;  // 232

    // encoder
    mma_gemm<128, 1, 0><<<dim3(4, MB), blk, SM_128>>>(x, wr + OFF_WE1, be1, h1, nullptr, nullptr, 512, 1024);
    mma_gemm<128, 0, 0><<<dim3(4, MB), blk, SM_128>>>(h1, wr + OFF_WE2, be2, h2, nullptr, nullptr, 512, 512);
    mma_gemm<128, 0, 0><<<dim3(16, MB), blk, SM_128>>>(h2, wr + OFF_WE3, be3, P, nullptr, nullptr, 2048, 512);
    mma_gemm<32, 0, 1><<<dim3(1, MB), blk, SM_32>>>(P, wr + OFF_WZ, bz, zb, nullptr, nullptr, 32, 2048);
    // decoder
    mma_gemm<128, 1, 0><<<dim3(16, MB), blk, SM_128>>>(zb, wr + OFF_WD1, bd1, P, nullptr, nullptr, 2048, 32);
    mma_gemm<128, 0, 0><<<dim3(4, MB), blk, SM_128>>>(P, wr + OFF_WD2, bd2, h1, nullptr, nullptr, 512, 2048);
    mma_gemm<128, 0, 0><<<dim3(4, MB), blk, SM_128>>>(h1, wr + OFF_WD3, bd3, h2, nullptr, nullptr, 512, 512);
    mma_gemm<128, 0, 2><<<dim3(8, MB), blk, SM_128>>>(h2, wr + OFF_WXB, bxb, nullptr, x, repart, 1024, 512);

    // clustering + rescue + loss
    cluster_pass<<<NBLK_PTS, 256>>>(t1, clu, out);
    rescue_kernel<<<148, 256, SM_RES>>>(x, t1, clu, We1, be1, We2, be2, We3, be3, Wz, bz, out);
    stats_kernel<<<1, 128>>>();
    kl_pass<<<NBLK_PTS, 256>>>();
    final_kernel<<<1, 256>>>(clu, out);

    int extra = out_size - (N_PTS + 1);
    if (extra > 0) fill_zero_kernel<<<(extra + 255) / 256, 256>>>(out + N_PTS + 1, extra);
}